// round 7
// baseline (speedup 1.0000x reference)
#include <cuda_runtime.h>
#include <math.h>
#include <stdint.h>

// Problem constants
#define BB 4
#define LL 2048
#define DD 1024
#define EE 8
#define HH 4096
#define TT 8192          // B*L tokens
#define TWOD 2048
#define EPSV 1e-6f

// GEMM tiling
#define BMq 128
#define BNq 128
#define BKq 16
#define AS_STRIDE 20     // BK + 4 pad (conflict-free for A frag reads)
#define BS_STRIDE 136    // BN + 8 pad (conflict-free for B frag reads)

// ---------------- device scratch (allocation-free rule: __device__ globals) ---
__device__ float g_cond[BB * TWOD];                       // (B, 2D)
__device__ float g_t[(size_t)TT * DD];                    // xn tokens (T, D)
__device__ float g_hs[(size_t)TT * HH];                   // shared expert hidden
__device__ float g_hr[(size_t)2 * TT * HH];               // routed hidden, row = pair id
__device__ int   g_cnt[EE];                               // per-expert token counts
__device__ int   g_list[EE * TT];                         // per-expert pair-id lists
__device__ float g_pairw[2 * TT];                         // combine weight per pair

// ---------------- helpers ----------------------------------------------------
__device__ __forceinline__ unsigned f2tf(float f) {
    unsigned u;
    asm("cvt.rna.tf32.f32 %0, %1;" : "=r"(u) : "f"(f));
    return u;
}

__device__ __forceinline__ float4 tf4(float4 v) {
    float4 o;
    o.x = __uint_as_float(f2tf(v.x));
    o.y = __uint_as_float(f2tf(v.y));
    o.z = __uint_as_float(f2tf(v.z));
    o.w = __uint_as_float(f2tf(v.w));
    return o;
}

__device__ __forceinline__ float geluf(float v) {
    // jax.nn.gelu default: tanh approximation
    float u = 0.7978845608028654f * (v + 0.044715f * v * v * v);
    return 0.5f * v * (1.0f + tanhf(u));
}

__device__ __forceinline__ void mma_tf32(float* c, const unsigned* a, const unsigned* b) {
    asm volatile(
        "mma.sync.aligned.m16n8k8.row.col.f32.tf32.tf32.f32 "
        "{%0,%1,%2,%3}, {%4,%5,%6,%7}, {%8,%9}, {%0,%1,%2,%3};\n"
        : "+f"(c[0]), "+f"(c[1]), "+f"(c[2]), "+f"(c[3])
        : "r"(a[0]), "r"(a[1]), "r"(a[2]), "r"(a[3]), "r"(b[0]), "r"(b[1]));
}

// ---------------- kernel: zero routing counters ------------------------------
__global__ void init_kernel() {
    if (threadIdx.x < EE) g_cnt[threadIdx.x] = 0;
}

// ---------------- kernel: cond = silu(time_c) @ ada_w + ada_b ----------------
__global__ void cond_kernel(const float* __restrict__ time_c,
                            const float* __restrict__ ada_w,
                            const float* __restrict__ ada_b) {
    __shared__ float s[DD];
    int b = blockIdx.y;
    for (int i = threadIdx.x; i < DD; i += blockDim.x) {
        float v = time_c[b * DD + i];
        s[i] = v / (1.0f + expf(-v));
    }
    __syncthreads();
    int col = blockIdx.x * 256 + threadIdx.x;  // 0..2047
    float acc = 0.0f;
#pragma unroll 4
    for (int r = 0; r < DD; r++) acc += s[r] * ada_w[r * TWOD + col];
    g_cond[b * TWOD + col] = acc + ada_b[col];
}

// ---------------- kernel: LN + modulate + router (one token per block) -------
__global__ void ln_route_kernel(const float* __restrict__ x,
                                const float* __restrict__ gate_w) {
    int tok = blockIdx.x;
    int b = tok / LL;
    const float* xr = x + (size_t)tok * DD;

    __shared__ float sx[DD];
    __shared__ float sred[16];
    __shared__ float smv[2];
    __shared__ float slog[EE];

    int tid = threadIdx.x, lane = tid & 31, w = tid >> 5;

    float lsum = 0.0f, lsq = 0.0f;
    for (int i = tid; i < DD; i += 256) {
        float v = xr[i];
        sx[i] = v;
        lsum += v;
        lsq += v * v;
    }
#pragma unroll
    for (int o = 16; o > 0; o >>= 1) {
        lsum += __shfl_down_sync(0xffffffffu, lsum, o);
        lsq  += __shfl_down_sync(0xffffffffu, lsq, o);
    }
    if (lane == 0) { sred[w] = lsum; sred[8 + w] = lsq; }
    __syncthreads();
    if (tid == 0) {
        float s = 0.0f, q = 0.0f;
        for (int i = 0; i < 8; i++) { s += sred[i]; q += sred[8 + i]; }
        float mean = s / (float)DD;
        float var = q / (float)DD - mean * mean;
        smv[0] = mean;
        smv[1] = rsqrtf(var + EPSV);
    }
    __syncthreads();
    float mean = smv[0], rstd = smv[1];
    const float* shiftp = g_cond + b * TWOD;
    const float* scalep = shiftp + DD;
    for (int i = tid; i < DD; i += 256) {
        float ln = (sx[i] - mean) * rstd;
        float xn = ln * (1.0f + scalep[i]) + shiftp[i];
        sx[i] = xn;
        g_t[(size_t)tok * DD + i] = xn;
    }
    __syncthreads();

    // router logits: warp w computes expert w (E=8 == number of warps)
    float acc = 0.0f;
    for (int r = lane; r < DD; r += 32) acc += sx[r] * gate_w[r * EE + w];
#pragma unroll
    for (int o = 16; o > 0; o >>= 1) acc += __shfl_down_sync(0xffffffffu, acc, o);
    if (lane == 0) slog[w] = acc;
    __syncthreads();

    if (tid == 0) {
        float m = slog[0];
        for (int e = 1; e < EE; e++) m = fmaxf(m, slog[e]);
        float p[EE];
        for (int e = 0; e < EE; e++) p[e] = expf(slog[e] - m);
        // top-2 (first occurrence on ties, matching jax top_k)
        int i0 = 0; float v0 = p[0];
        for (int e = 1; e < EE; e++) if (p[e] > v0) { v0 = p[e]; i0 = e; }
        int i1 = -1; float v1 = -1.0f;
        for (int e = 0; e < EE; e++) if (e != i0 && p[e] > v1) { v1 = p[e]; i1 = e; }
        float inv = 1.0f / (v0 + v1);
        float w0 = v0 * inv, w1 = v1 * inv;  // softmax denom cancels in renorm
        int pos0 = atomicAdd(&g_cnt[i0], 1);
        g_list[i0 * TT + pos0] = tok * 2;
        int pos1 = atomicAdd(&g_cnt[i1], 1);
        g_list[i1 * TT + pos1] = tok * 2 + 1;
        g_pairw[tok * 2] = w0;
        g_pairw[tok * 2 + 1] = w1;
    }
}

// ---------------- tf32 tensor-core GEMM --------------------------------------
// C(MxN) = gather(A)(MxK) @ W(KxN), epilogues:
//   FFN1: Out[orow] = gelu(acc + bias)           (store hidden)
//   FFN2 shared: Out[orow] = xres + acc + bias   (initialize output w/ residual)
//   FFN2 routed: atomicAdd(Out[orow], w*(acc+bias))
template <bool ROUTED, bool FFN2>
__global__ __launch_bounds__(256)
void gemm_kernel(const float* __restrict__ Abase,
                 const float* __restrict__ Wbase,
                 const float* __restrict__ biasbase,
                 const float* __restrict__ xres,
                 float* __restrict__ Out,
                 int Kdim, int Ndim) {
    int e = ROUTED ? blockIdx.z : 0;
    int n_rows = ROUTED ? g_cnt[e] : TT;
    int m0 = blockIdx.y * BMq;
    if (ROUTED && m0 >= n_rows) return;
    int n0 = blockIdx.x * BNq;
    const float* W = Wbase + (ROUTED ? (size_t)e * Kdim * Ndim : 0);
    const float* bias = biasbase + (ROUTED ? (size_t)e * Ndim : 0);

    __shared__ float As[2][BMq * AS_STRIDE];
    __shared__ float Bs[2][BKq * BS_STRIDE];
    __shared__ int srow[BMq];
    __shared__ int sorow[BMq];
    __shared__ float swt[BMq];

    int tid = threadIdx.x;
    if (tid < BMq) {
        int i = m0 + tid;
        int arow, orow;
        float wv = 1.0f;
        if (ROUTED) {
            bool valid = i < n_rows;
            int pair = valid ? g_list[e * TT + i] : 0;
            if (!FFN2) { arow = pair >> 1; orow = pair; }
            else       { arow = pair;      orow = pair >> 1; wv = g_pairw[pair]; }
            if (!valid) { arow = -1; orow = -1; }
        } else {
            arow = i; orow = i;
        }
        srow[tid] = arow;
        sorow[tid] = orow;
        swt[tid] = wv;
    }
    __syncthreads();

    // global->reg load mapping (512 float4 per tile, 2 per thread)
    int a_r0 = tid >> 2, a_c = (tid & 3) * 4;
    int a_r1 = a_r0 + 64;
    int b_r0 = tid >> 5, b_c = (tid & 31) * 4;
    int b_r1 = b_r0 + 8;

    int wid = tid >> 5, lane = tid & 31;
    int wm = wid & 3, wn = wid >> 2;   // warp tile 32(m) x 64(n)
    int lrow = lane >> 2, lcol = lane & 3;

    float acc[2][8][4];
#pragma unroll
    for (int a = 0; a < 2; a++)
#pragma unroll
        for (int bq = 0; bq < 8; bq++)
#pragma unroll
            for (int c = 0; c < 4; c++) acc[a][bq][c] = 0.0f;

    int NK = Kdim / BKq;
    float4 ra0, ra1, rb0, rb1;

    // prologue: load k-tile 0
    {
        int k0 = 0;
        int r = srow[a_r0];
        ra0 = (r >= 0) ? *(const float4*)(Abase + (size_t)r * Kdim + k0 + a_c)
                       : make_float4(0.f, 0.f, 0.f, 0.f);
        r = srow[a_r1];
        ra1 = (r >= 0) ? *(const float4*)(Abase + (size_t)r * Kdim + k0 + a_c)
                       : make_float4(0.f, 0.f, 0.f, 0.f);
        rb0 = *(const float4*)(W + (size_t)(k0 + b_r0) * Ndim + n0 + b_c);
        rb1 = *(const float4*)(W + (size_t)(k0 + b_r1) * Ndim + n0 + b_c);
        *(float4*)&As[0][a_r0 * AS_STRIDE + a_c] = tf4(ra0);
        *(float4*)&As[0][a_r1 * AS_STRIDE + a_c] = tf4(ra1);
        *(float4*)&Bs[0][b_r0 * BS_STRIDE + b_c] = tf4(rb0);
        *(float4*)&Bs[0][b_r1 * BS_STRIDE + b_c] = tf4(rb1);
    }
    __syncthreads();

    for (int kt = 0; kt < NK; kt++) {
        int buf = kt & 1;
        if (kt + 1 < NK) {
            int k0 = (kt + 1) * BKq;
            int r = srow[a_r0];
            ra0 = (r >= 0) ? *(const float4*)(Abase + (size_t)r * Kdim + k0 + a_c)
                           : make_float4(0.f, 0.f, 0.f, 0.f);
            r = srow[a_r1];
            ra1 = (r >= 0) ? *(const float4*)(Abase + (size_t)r * Kdim + k0 + a_c)
                           : make_float4(0.f, 0.f, 0.f, 0.f);
            rb0 = *(const float4*)(W + (size_t)(k0 + b_r0) * Ndim + n0 + b_c);
            rb1 = *(const float4*)(W + (size_t)(k0 + b_r1) * Ndim + n0 + b_c);
        }

        // compute on As[buf]/Bs[buf]
        {
            const float* as = As[buf];
            const float* bs = Bs[buf];
#pragma unroll
            for (int kk = 0; kk < 2; kk++) {
                int k8 = kk * 8;
                unsigned af[2][4];
#pragma unroll
                for (int tm = 0; tm < 2; tm++) {
                    const float* p = as + (wm * 32 + tm * 16 + lrow) * AS_STRIDE + k8 + lcol;
                    af[tm][0] = __float_as_uint(p[0]);
                    af[tm][1] = __float_as_uint(p[8 * AS_STRIDE]);
                    af[tm][2] = __float_as_uint(p[4]);
                    af[tm][3] = __float_as_uint(p[8 * AS_STRIDE + 4]);
                }
                unsigned bf[8][2];
#pragma unroll
                for (int tn = 0; tn < 8; tn++) {
                    const float* p = bs + (k8 + lcol) * BS_STRIDE + wn * 64 + tn * 8 + lrow;
                    bf[tn][0] = __float_as_uint(p[0]);
                    bf[tn][1] = __float_as_uint(p[4 * BS_STRIDE]);
                }
#pragma unroll
                for (int tm = 0; tm < 2; tm++)
#pragma unroll
                    for (int tn = 0; tn < 8; tn++)
                        mma_tf32(acc[tm][tn], af[tm], bf[tn]);
            }
        }

        if (kt + 1 < NK) {
            *(float4*)&As[buf ^ 1][a_r0 * AS_STRIDE + a_c] = tf4(ra0);
            *(float4*)&As[buf ^ 1][a_r1 * AS_STRIDE + a_c] = tf4(ra1);
            *(float4*)&Bs[buf ^ 1][b_r0 * BS_STRIDE + b_c] = tf4(rb0);
            *(float4*)&Bs[buf ^ 1][b_r1 * BS_STRIDE + b_c] = tf4(rb1);
            __syncthreads();
        }
    }

    // epilogue
#pragma unroll
    for (int tm = 0; tm < 2; tm++) {
#pragma unroll
        for (int rr = 0; rr < 2; rr++) {
            int li = wm * 32 + tm * 16 + rr * 8 + lrow;
            int orow = sorow[li];
            if (orow < 0) continue;
            float wv = swt[li];
#pragma unroll
            for (int tn = 0; tn < 8; tn++) {
                int col = n0 + wn * 64 + tn * 8 + lcol * 2;
                float c0 = acc[tm][tn][rr * 2 + 0];
                float c1 = acc[tm][tn][rr * 2 + 1];
                if (!FFN2) {
                    Out[(size_t)orow * Ndim + col]     = geluf(c0 + bias[col]);
                    Out[(size_t)orow * Ndim + col + 1] = geluf(c1 + bias[col + 1]);
                } else if (!ROUTED) {
                    size_t o = (size_t)orow * Ndim + col;
                    Out[o]     = xres[o]     + c0 + bias[col];
                    Out[o + 1] = xres[o + 1] + c1 + bias[col + 1];
                } else {
                    size_t o = (size_t)orow * Ndim + col;
                    atomicAdd(&Out[o],     wv * (c0 + bias[col]));
                    atomicAdd(&Out[o + 1], wv * (c1 + bias[col + 1]));
                }
            }
        }
    }
}

// ---------------- launch -----------------------------------------------------
extern "C" void kernel_launch(void* const* d_in, const int* in_sizes, int n_in,
                              void* d_out, int out_size) {
    const float* x      = (const float*)d_in[0];
    const float* time_c = (const float*)d_in[1];
    const float* ada_w  = (const float*)d_in[2];
    const float* ada_b  = (const float*)d_in[3];
    const float* gate_w = (const float*)d_in[4];
    const float* w1     = (const float*)d_in[5];
    const float* b1     = (const float*)d_in[6];
    const float* w2     = (const float*)d_in[7];
    const float* b2     = (const float*)d_in[8];
    const float* sw1    = (const float*)d_in[9];
    const float* sb1    = (const float*)d_in[10];
    const float* sw2    = (const float*)d_in[11];
    const float* sb2    = (const float*)d_in[12];
    float* out = (float*)d_out;

    float *p_t = nullptr, *p_hs = nullptr, *p_hr = nullptr;
    cudaGetSymbolAddress((void**)&p_t, g_t);
    cudaGetSymbolAddress((void**)&p_hs, g_hs);
    cudaGetSymbolAddress((void**)&p_hr, g_hr);

    init_kernel<<<1, 32>>>();
    cond_kernel<<<dim3(TWOD / 256, BB), 256>>>(time_c, ada_w, ada_b);
    ln_route_kernel<<<TT, 256>>>(x, gate_w);

    // shared FFN1: hs = gelu(t @ sw1 + sb1)
    gemm_kernel<false, false><<<dim3(HH / BNq, TT / BMq, 1), 256>>>(
        p_t, sw1, sb1, nullptr, p_hs, DD, HH);
    // routed FFN1: hr[pair] = gelu(t[tok] @ w1[e] + b1[e])
    gemm_kernel<true, false><<<dim3(HH / BNq, TT / BMq, EE), 256>>>(
        p_t, w1, b1, nullptr, p_hr, DD, HH);
    // shared FFN2 (+ residual): out = x + hs @ sw2 + sb2
    gemm_kernel<false, true><<<dim3(DD / BNq, TT / BMq, 1), 256>>>(
        p_hs, sw2, sb2, x, out, HH, DD);
    // routed FFN2: out[tok] += w * (hr[pair] @ w2[e] + b2[e])
    gemm_kernel<true, true><<<dim3(DD / BNq, TT / BMq, EE), 256>>>(
        p_hr, w2, b2, nullptr, out, HH, DD);
}

// round 11
// speedup vs baseline: 1.1804x; 1.1804x over previous
#include <cuda_runtime.h>
#include <math.h>
#include <stdint.h>

// Problem constants
#define BB 4
#define LL 2048
#define DD 1024
#define EE 8
#define HH 4096
#define TT 8192
#define TWOD 2048
#define EPSV 1e-6f

// GEMM tiling: CTA 128M x 128N, BK=16, 4-stage cp.async pipeline
#define STAGES 4
#define AROW 24                 // A smem row stride (floats): 16 data + 8 pad
#define BQ_STRIDE 264           // B smem per-(k&3) plane stride (floats)
#define BKK_STRIDE 1056         // 4 * BQ_STRIDE
#define AOFF_B 3072             // A stage = 128*24 floats
#define STAGE_F 5184            // 3072 + 2112 floats per stage
#define SMEM_FLOATS (STAGES * STAGE_F)
#define SMEM_BYTES (SMEM_FLOATS * 4 + 2048)   // + metadata

// ---------------- device scratch ---------------------------------------------
__device__ float g_cond[BB * TWOD];
__device__ float g_t[(size_t)TT * DD];           // xn tokens, tf32-rounded, perm16 layout
__device__ float g_hs[(size_t)TT * HH];          // shared hidden, rounded, perm16
__device__ float g_hr[(size_t)2 * TT * HH];      // routed hidden (row = pair id), perm16
__device__ int   g_cnt[EE];
__device__ int   g_list[EE * TT];
__device__ float g_pairw[2 * TT];
// preprocessed weights: tf32-rounded, pair-interleaved plane layout
__device__ float g_sw1P[(size_t)DD * HH];
__device__ float g_sw2P[(size_t)HH * DD];
__device__ float g_w1P[(size_t)EE * DD * HH];
__device__ float g_w2P[(size_t)EE * HH * DD];

// ---------------- helpers ----------------------------------------------------
__device__ __forceinline__ unsigned f2tf(float f) {
    unsigned u;
    asm("cvt.rna.tf32.f32 %0, %1;" : "=r"(u) : "f"(f));
    return u;
}

__device__ __forceinline__ float geluf(float v) {
    float u = 0.7978845608028654f * (v + 0.044715f * v * v * v);
    return 0.5f * v * (1.0f + tanhf(u));
}

__device__ __forceinline__ uint32_t smem_u32(const void* p) {
    uint32_t a;
    asm("{ .reg .u64 t; cvta.to.shared.u64 t, %1; cvt.u32.u64 %0, t; }"
        : "=r"(a) : "l"(p));
    return a;
}

// perm16: position of logical k within its 16-group (pairs k,k+4 adjacent)
__device__ __forceinline__ int p16(int k) {
    return (k & 8) | ((k & 3) << 1) | ((k >> 2) & 1);
}

__device__ __forceinline__ void mma_tf32(float* c, const unsigned* a, const unsigned* b) {
    asm volatile(
        "mma.sync.aligned.m16n8k8.row.col.f32.tf32.tf32.f32 "
        "{%0,%1,%2,%3}, {%4,%5,%6,%7}, {%8,%9}, {%0,%1,%2,%3};\n"
        : "+f"(c[0]), "+f"(c[1]), "+f"(c[2]), "+f"(c[3])
        : "r"(a[0]), "r"(a[1]), "r"(a[2]), "r"(a[3]), "r"(b[0]), "r"(b[1]));
}

__device__ __forceinline__ void cpa16(uint32_t s, const float* g) {
    asm volatile("cp.async.cg.shared.global [%0], [%1], 16;" :: "r"(s), "l"(g)
                 : "memory");
}
#define CP_COMMIT() asm volatile("cp.async.commit_group;" ::: "memory")

// ---------------- small kernels ----------------------------------------------
__global__ void init_kernel() {
    if (threadIdx.x < EE) g_cnt[threadIdx.x] = 0;
}

__global__ void cond_kernel(const float* __restrict__ time_c,
                            const float* __restrict__ ada_w,
                            const float* __restrict__ ada_b) {
    __shared__ float s[DD];
    int b = blockIdx.y;
    for (int i = threadIdx.x; i < DD; i += blockDim.x) {
        float v = time_c[b * DD + i];
        s[i] = v / (1.0f + expf(-v));
    }
    __syncthreads();
    int col = blockIdx.x * 256 + threadIdx.x;
    float acc = 0.0f;
#pragma unroll 4
    for (int r = 0; r < DD; r++) acc += s[r] * ada_w[r * TWOD + col];
    g_cond[b * TWOD + col] = acc + ada_b[col];
}

__global__ void ln_route_kernel(const float* __restrict__ x,
                                const float* __restrict__ gate_w) {
    int tok = blockIdx.x;
    int b = tok / LL;
    const float* xr = x + (size_t)tok * DD;
    __shared__ float sx[DD];
    __shared__ float sred[16];
    __shared__ float smv[2];
    __shared__ float slog[EE];
    int tid = threadIdx.x, lane = tid & 31, w = tid >> 5;
    float lsum = 0.0f, lsq = 0.0f;
    for (int i = tid; i < DD; i += 256) {
        float v = xr[i];
        sx[i] = v; lsum += v; lsq += v * v;
    }
#pragma unroll
    for (int o = 16; o > 0; o >>= 1) {
        lsum += __shfl_down_sync(0xffffffffu, lsum, o);
        lsq  += __shfl_down_sync(0xffffffffu, lsq, o);
    }
    if (lane == 0) { sred[w] = lsum; sred[8 + w] = lsq; }
    __syncthreads();
    if (tid == 0) {
        float s = 0.0f, q = 0.0f;
        for (int i = 0; i < 8; i++) { s += sred[i]; q += sred[8 + i]; }
        float mean = s / (float)DD;
        float var = q / (float)DD - mean * mean;
        smv[0] = mean; smv[1] = rsqrtf(var + EPSV);
    }
    __syncthreads();
    float mean = smv[0], rstd = smv[1];
    const float* shiftp = g_cond + b * TWOD;
    const float* scalep = shiftp + DD;
    for (int i = tid; i < DD; i += 256) {
        float ln = (sx[i] - mean) * rstd;
        float xn = ln * (1.0f + scalep[i]) + shiftp[i];
        sx[i] = xn;
        // tf32-rounded, perm16-interleaved layout for the GEMM A-side
        g_t[(size_t)tok * DD + ((i & ~15) | p16(i & 15))] = __uint_as_float(f2tf(xn));
    }
    __syncthreads();
    float acc = 0.0f;
    for (int r = lane; r < DD; r += 32) acc += sx[r] * gate_w[r * EE + w];
#pragma unroll
    for (int o = 16; o > 0; o >>= 1) acc += __shfl_down_sync(0xffffffffu, acc, o);
    if (lane == 0) slog[w] = acc;
    __syncthreads();
    if (tid == 0) {
        float m = slog[0];
        for (int e = 1; e < EE; e++) m = fmaxf(m, slog[e]);
        float p[EE];
        for (int e = 0; e < EE; e++) p[e] = expf(slog[e] - m);
        int i0 = 0; float v0 = p[0];
        for (int e = 1; e < EE; e++) if (p[e] > v0) { v0 = p[e]; i0 = e; }
        int i1 = -1; float v1 = -1.0f;
        for (int e = 0; e < EE; e++) if (e != i0 && p[e] > v1) { v1 = p[e]; i1 = e; }
        float inv = 1.0f / (v0 + v1);
        int pos0 = atomicAdd(&g_cnt[i0], 1);
        g_list[i0 * TT + pos0] = tok * 2;
        int pos1 = atomicAdd(&g_cnt[i1], 1);
        g_list[i1 * TT + pos1] = tok * 2 + 1;
        g_pairw[tok * 2] = v0 * inv;
        g_pairw[tok * 2 + 1] = v1 * inv;
    }
}

// Preprocess weights [K][N] -> plane layout: plane = kt*8 + kk*4 + q holds
// (k = kt*16 + kk*8 + p*4 + q) as [n][pair p] float2, tf32-rounded.
__global__ void prep_w(const float* __restrict__ W, float* __restrict__ Wp,
                       int Kd, int Nd) {
    int e = blockIdx.z;
    const float* w = W + (size_t)e * Kd * Nd;
    float* wp = Wp + (size_t)e * Kd * Nd;
    int plane = blockIdx.y;                    // 0 .. Kd/2-1
    int kt = plane >> 3, r = plane & 7, kk = r >> 2, q = r & 3;
    int k0 = kt * 16 + kk * 8 + q;
    int n = blockIdx.x * 256 + threadIdx.x;
    float2 o;
    o.x = __uint_as_float(f2tf(w[(size_t)k0 * Nd + n]));
    o.y = __uint_as_float(f2tf(w[(size_t)(k0 + 4) * Nd + n]));
    *(float2*)(wp + ((size_t)plane * Nd + n) * 2) = o;
}

// ---------------- cp.async + LDS.64 tf32 mma GEMM ----------------------------
// C[128 x 128] per CTA = gather(A)[128xK] @ W[KxN] (W in plane layout)
template <bool ROUTED, bool FFN2>
__global__ __launch_bounds__(256, 2)
void gemm_cp(const float* __restrict__ A, const float* __restrict__ Wp,
             const float* __restrict__ biasbase, const float* __restrict__ xres,
             float* __restrict__ Out, int Kdim, int Ndim) {
    int e = ROUTED ? blockIdx.z : 0;
    int n_rows = ROUTED ? g_cnt[e] : TT;
    int m0 = blockIdx.y * 128;
    if (ROUTED && m0 >= n_rows) return;
    int n0 = blockIdx.x * 128;
    const float* W = Wp + (ROUTED ? (size_t)e * Kdim * Ndim : 0);
    const float* bias = biasbase + (ROUTED ? (size_t)e * Ndim : 0);

    extern __shared__ __align__(16) float sm[];
    int* srow = (int*)(sm + SMEM_FLOATS);
    int* sorow = srow + 128;
    float* swt = (float*)(sorow + 128);
    float* sbias = swt + 128;
    uint32_t sb = smem_u32(sm);

    int tid = threadIdx.x;
    if (tid < 128) {
        int i = m0 + tid;
        int arow, orow; float wv = 1.0f;
        if (ROUTED) {
            bool valid = i < n_rows;
            int pair = valid ? g_list[e * TT + i] : 0;
            if (!FFN2) { arow = pair >> 1; orow = pair; }
            else       { arow = pair;      orow = pair >> 1; wv = g_pairw[pair]; }
            if (!valid) orow = -1;
        } else { arow = i; orow = i; }
        srow[tid] = arow; sorow[tid] = orow; swt[tid] = wv;
        sbias[tid] = bias[n0 + tid];
    }
    __syncthreads();

    // cp.async mappings: 2 A chunks + 2 B chunks per thread per k-tile
    int am0 = tid >> 2, aj = tid & 3;       // A chunk c=tid  -> (m, j)
    int am1 = am0 + 64;                     // A chunk c=tid+256
    unsigned asrc0 = (unsigned)srow[am0] * (unsigned)Kdim + aj * 4;
    unsigned asrc1 = (unsigned)srow[am1] * (unsigned)Kdim + aj * 4;
    uint32_t adst0 = sb + (uint32_t)(am0 * AROW + aj * 4) * 4;
    uint32_t adst1 = sb + (uint32_t)(am1 * AROW + aj * 4) * 4;
    int bp0 = tid >> 6, bj = tid & 63;      // B chunk c=tid  -> (plane, jj)
    int bp1 = bp0 + 4;                      // B chunk c=tid+256
    unsigned bsrc0 = (unsigned)bp0 * (unsigned)(Ndim * 2) + n0 * 2 + bj * 4;
    unsigned bsrc1 = (unsigned)bp1 * (unsigned)(Ndim * 2) + n0 * 2 + bj * 4;
    uint32_t bdst0 = sb + (uint32_t)(AOFF_B + (bp0 >> 2) * BKK_STRIDE +
                                     (bp0 & 3) * BQ_STRIDE + bj * 4) * 4;
    uint32_t bdst1 = sb + (uint32_t)(AOFF_B + (bp1 >> 2) * BKK_STRIDE +
                                     (bp1 & 3) * BQ_STRIDE + bj * 4) * 4;

#define ISSUE(kt_, st_) do {                                                   \
    uint32_t _so = (uint32_t)(st_) * (STAGE_F * 4);                            \
    unsigned _ka = (unsigned)(kt_) * 16u;                                      \
    unsigned _kb = (unsigned)(kt_) * 16u * (unsigned)Ndim;                     \
    cpa16(adst0 + _so, A + asrc0 + _ka);                                       \
    cpa16(adst1 + _so, A + asrc1 + _ka);                                       \
    cpa16(bdst0 + _so, W + bsrc0 + _kb);                                       \
    cpa16(bdst1 + _so, W + bsrc1 + _kb);                                       \
} while (0)

    int NK = Kdim / 16;
    ISSUE(0, 0); CP_COMMIT();
    ISSUE(1, 1); CP_COMMIT();
    ISSUE(2, 2); CP_COMMIT();

    int wid = tid >> 5, lane = tid & 31;
    int wm = wid & 3, wn = wid >> 2;        // warp tile 32m x 64n
    int lrow = lane >> 2, lcol = lane & 3;

    float acc[2][8][4];
#pragma unroll
    for (int a = 0; a < 2; a++)
#pragma unroll
        for (int b = 0; b < 8; b++)
#pragma unroll
            for (int c = 0; c < 4; c++) acc[a][b][c] = 0.0f;

    // fragment base addresses (bytes)
    uint32_t a_base = sb + (uint32_t)((wm * 32 + lrow) * AROW + lcol * 2) * 4;
    uint32_t b_base = sb + (uint32_t)(AOFF_B + lcol * BQ_STRIDE +
                                      (wn * 64 + lrow) * 2) * 4;

    for (int kt = 0; kt < NK; kt++) {
        asm volatile("cp.async.wait_group 2;" ::: "memory");
        __syncthreads();
        int kl = kt + STAGES - 1;
        if (kl < NK) { ISSUE(kl, kl & 3); }
        CP_COMMIT();
        uint32_t soff = (uint32_t)(kt & 3) * (STAGE_F * 4);
#pragma unroll
        for (int kk = 0; kk < 2; kk++) {
            uint32_t ab = a_base + soff + kk * 32;          // kk*8 floats
            uint32_t bb = b_base + soff + kk * (BKK_STRIDE * 4);
            unsigned af[2][4];
#pragma unroll
            for (int tm = 0; tm < 2; tm++) {
                uint32_t p = ab + tm * (16 * AROW * 4);
                asm volatile("ld.shared.v2.b32 {%0,%1}, [%2];"
                             : "=r"(af[tm][0]), "=r"(af[tm][2]) : "r"(p));
                asm volatile("ld.shared.v2.b32 {%0,%1}, [%2];"
                             : "=r"(af[tm][1]), "=r"(af[tm][3])
                             : "r"(p + 8 * AROW * 4));
            }
            unsigned bf[8][2];
#pragma unroll
            for (int tn = 0; tn < 8; tn++) {
                asm volatile("ld.shared.v2.b32 {%0,%1}, [%2];"
                             : "=r"(bf[tn][0]), "=r"(bf[tn][1])
                             : "r"(bb + tn * 64));
            }
#pragma unroll
            for (int tm = 0; tm < 2; tm++)
#pragma unroll
                for (int tn = 0; tn < 8; tn++)
                    mma_tf32(acc[tm][tn], af[tm], bf[tn]);
        }
    }
#undef ISSUE

    // epilogue
#pragma unroll
    for (int tm = 0; tm < 2; tm++) {
#pragma unroll
        for (int rr = 0; rr < 2; rr++) {
            int li = wm * 32 + tm * 16 + rr * 8 + lrow;
            int orow = sorow[li];
            if (orow < 0) continue;
            float wv = swt[li];
            float* orp = Out + (size_t)orow * Ndim;
#pragma unroll
            for (int tn = 0; tn < 8; tn++) {
                int c0 = wn * 64 + tn * 8 + lcol * 2;       // logical col in tile
                float v0 = acc[tm][tn][rr * 2 + 0] + sbias[c0];
                float v1 = acc[tm][tn][rr * 2 + 1] + sbias[c0 + 1];
                if (!FFN2) {
                    // hidden: gelu + tf32 round, store PERMUTED (consumed as A)
                    int pc0 = (c0 & ~15) | p16(c0 & 15);
                    int pc1 = ((c0 + 1) & ~15) | p16((c0 + 1) & 15);
                    orp[n0 + pc0] = __uint_as_float(f2tf(geluf(v0)));
                    orp[n0 + pc1] = __uint_as_float(f2tf(geluf(v1)));
                } else if (!ROUTED) {
                    size_t o = (size_t)orow * Ndim + n0 + c0;
                    Out[o]     = xres[o]     + v0;
                    Out[o + 1] = xres[o + 1] + v1;
                } else {
                    atomicAdd(orp + n0 + c0,     wv * v0);
                    atomicAdd(orp + n0 + c0 + 1, wv * v1);
                }
            }
        }
    }
}

// ---------------- launch -----------------------------------------------------
extern "C" void kernel_launch(void* const* d_in, const int* in_sizes, int n_in,
                              void* d_out, int out_size) {
    const float* x      = (const float*)d_in[0];
    const float* time_c = (const float*)d_in[1];
    const float* ada_w  = (const float*)d_in[2];
    const float* ada_b  = (const float*)d_in[3];
    const float* gate_w = (const float*)d_in[4];
    const float* w1     = (const float*)d_in[5];
    const float* b1     = (const float*)d_in[6];
    const float* w2     = (const float*)d_in[7];
    const float* b2     = (const float*)d_in[8];
    const float* sw1    = (const float*)d_in[9];
    const float* sb1    = (const float*)d_in[10];
    const float* sw2    = (const float*)d_in[11];
    const float* sb2    = (const float*)d_in[12];
    float* out = (float*)d_out;

    float *p_t, *p_hs, *p_hr, *p_sw1P, *p_sw2P, *p_w1P, *p_w2P;
    cudaGetSymbolAddress((void**)&p_t, g_t);
    cudaGetSymbolAddress((void**)&p_hs, g_hs);
    cudaGetSymbolAddress((void**)&p_hr, g_hr);
    cudaGetSymbolAddress((void**)&p_sw1P, g_sw1P);
    cudaGetSymbolAddress((void**)&p_sw2P, g_sw2P);
    cudaGetSymbolAddress((void**)&p_w1P, g_w1P);
    cudaGetSymbolAddress((void**)&p_w2P, g_w2P);

    cudaFuncSetAttribute(gemm_cp<false, false>,
                         cudaFuncAttributeMaxDynamicSharedMemorySize, SMEM_BYTES);
    cudaFuncSetAttribute(gemm_cp<true, false>,
                         cudaFuncAttributeMaxDynamicSharedMemorySize, SMEM_BYTES);
    cudaFuncSetAttribute(gemm_cp<false, true>,
                         cudaFuncAttributeMaxDynamicSharedMemorySize, SMEM_BYTES);
    cudaFuncSetAttribute(gemm_cp<true, true>,
                         cudaFuncAttributeMaxDynamicSharedMemorySize, SMEM_BYTES);

    init_kernel<<<1, 32>>>();
    cond_kernel<<<dim3(TWOD / 256, BB), 256>>>(time_c, ada_w, ada_b);
    ln_route_kernel<<<TT, 256>>>(x, gate_w);

    // weight preprocessing (tf32 round + interleave)
    prep_w<<<dim3(HH / 256, DD / 2, 1), 256>>>(sw1, p_sw1P, DD, HH);
    prep_w<<<dim3(DD / 256, HH / 2, 1), 256>>>(sw2, p_sw2P, HH, DD);
    prep_w<<<dim3(HH / 256, DD / 2, EE), 256>>>(w1, p_w1P, DD, HH);
    prep_w<<<dim3(DD / 256, HH / 2, EE), 256>>>(w2, p_w2P, HH, DD);

    // shared FFN1: hs = tf32(gelu(t @ sw1 + sb1))
    gemm_cp<false, false><<<dim3(HH / 128, TT / 128, 1), 256, SMEM_BYTES>>>(
        p_t, p_sw1P, sb1, nullptr, p_hs, DD, HH);
    // routed FFN1: hr[pair] = tf32(gelu(t[tok] @ w1[e] + b1[e]))
    gemm_cp<true, false><<<dim3(HH / 128, TT / 128, EE), 256, SMEM_BYTES>>>(
        p_t, p_w1P, b1, nullptr, p_hr, DD, HH);
    // shared FFN2 (+residual init): out = x + hs @ sw2 + sb2
    gemm_cp<false, true><<<dim3(DD / 128, TT / 128, 1), 256, SMEM_BYTES>>>(
        p_hs, p_sw2P, sb2, x, out, HH, DD);
    // routed FFN2: out[tok] += w * (hr[pair] @ w2[e] + b2[e])
    gemm_cp<true, true><<<dim3(DD / 128, TT / 128, EE), 256, SMEM_BYTES>>>(
        p_hr, p_w2P, b2, nullptr, out, HH, DD);
}

// round 13
// speedup vs baseline: 1.4036x; 1.1891x over previous
#include <cuda_runtime.h>
#include <math.h>
#include <stdint.h>

// Problem constants
#define BB 4
#define LL 2048
#define DD 1024
#define EE 8
#define HH 4096
#define TT 8192
#define TWOD 2048
#define EPSV 1e-6f
#define RPAD 17536              // padded routed rows (128-aligned expert segments)

// GEMM: CTA 128M x 128N, stage = 32 K (two 16-k planes), 3 stages
#define STAGE_BYTES 32768
#define NSTAGE 3
#define OFF_META (NSTAGE * STAGE_BYTES)          // 98304
#define SMEM_DYN (OFF_META + 2048)               // 100352 bytes

// ---------------- device scratch ---------------------------------------------
__device__ float g_cond[BB * TWOD];
__device__ float g_tp[(size_t)64 * TT * 16];          // xn tokens, plane layout
__device__ float g_tr[(size_t)64 * RPAD * 16];        // gathered tokens (p-order)
__device__ float g_hsp[(size_t)256 * TT * 16];        // shared hidden planes
__device__ float g_hrp[(size_t)256 * RPAD * 16];      // routed hidden planes
__device__ float g_sw1P[(size_t)64 * HH * 16];
__device__ float g_sw2P[(size_t)256 * DD * 16];
__device__ float g_w1P[(size_t)EE * 64 * HH * 16];
__device__ float g_w2P[(size_t)EE * 256 * DD * 16];
__device__ int   g_cnt[EE];
__device__ int   g_off[EE + 1];                       // 128-aligned starts
__device__ int   g_end[EE];                           // true ends
__device__ int   g_list[EE * TT];
__device__ float g_pairw[2 * TT];
__device__ int   g_ptok[RPAD];
__device__ float g_pw[RPAD];

// ---------------- helpers ----------------------------------------------------
__device__ __forceinline__ unsigned f2tf(float f) {
    unsigned u;
    asm("cvt.rna.tf32.f32 %0, %1;" : "=r"(u) : "f"(f));
    return u;
}

__device__ __forceinline__ float geluf(float v) {
    float u = 0.7978845608028654f * (v + 0.044715f * v * v * v);
    return 0.5f * v * (1.0f + tanhf(u));
}

__device__ __forceinline__ uint32_t smem_u32(const void* p) {
    uint32_t a;
    asm("{ .reg .u64 t; cvta.to.shared.u64 t, %1; cvt.u32.u64 %0, t; }"
        : "=r"(a) : "l"(p));
    return a;
}

// word index (0..15) of logical k (0..15) within a 64B plane-row of row r.
// pairs (k, k+4) adjacent; kk-halves swapped by row bit1 for bank spread.
// NOTE: row-dependent (bit1 of r) — all tile bases must be 128-aligned so the
// consumer's tile-local row is congruent to the producer's global row mod 4.
__device__ __forceinline__ int word16(int r, int k) {
    int pos = (k & 8) | ((k & 3) << 1) | ((k >> 2) & 1);
    return ((((pos >> 3) ^ (r >> 1)) & 1) << 3) | (pos & 7);
}

__device__ __forceinline__ void mma_tf32(float* c, const unsigned* a, const unsigned* b) {
    asm volatile(
        "mma.sync.aligned.m16n8k8.row.col.f32.tf32.tf32.f32 "
        "{%0,%1,%2,%3}, {%4,%5,%6,%7}, {%8,%9}, {%0,%1,%2,%3};\n"
        : "+f"(c[0]), "+f"(c[1]), "+f"(c[2]), "+f"(c[3])
        : "r"(a[0]), "r"(a[1]), "r"(a[2]), "r"(a[3]), "r"(b[0]), "r"(b[1]));
}

#define MBAR_INIT(a, cnt) \
    asm volatile("mbarrier.init.shared.b64 [%0], %1;" :: "r"(a), "r"(cnt) : "memory")

#define EXPECT_TX(mbar, n) \
    asm volatile("mbarrier.arrive.expect_tx.shared.b64 _, [%0], %1;" \
                 :: "r"(mbar), "r"(n) : "memory")

#define BULK8K(dst, src, mbar) \
    asm volatile("cp.async.bulk.shared::cluster.global.mbarrier::complete_tx::bytes " \
                 "[%0], [%1], %2, [%3];" \
                 :: "r"(dst), "l"(src), "r"(8192u), "r"(mbar) : "memory")

#define MBAR_WAIT(mbar, par) do {                                              \
    uint32_t _m = (mbar); uint32_t _p = (par); uint32_t _d;                    \
    asm volatile("{\n\t.reg .pred p;\n\t"                                      \
        "mbarrier.try_wait.parity.acquire.cta.shared::cta.b64 p, [%1], %2;\n\t"\
        "selp.b32 %0, 1, 0, p;\n\t}" : "=r"(_d) : "r"(_m), "r"(_p) : "memory");\
    if (!_d) {                                                                 \
        asm volatile("{\n\t.reg .pred P1;\n\t"                                 \
            "W0_%=:\n\t"                                                       \
            "mbarrier.try_wait.parity.acquire.cta.shared::cta.b64 P1, [%0], %1, 0x989680;\n\t" \
            "@P1 bra.uni W1_%=;\n\t"                                           \
            "bra.uni W0_%=;\n\t"                                               \
            "W1_%=:\n\t}" :: "r"(_m), "r"(_p) : "memory");                     \
    }                                                                          \
} while (0)

// ---------------- small kernels ----------------------------------------------
__global__ void init_kernel() {
    if (threadIdx.x < EE) g_cnt[threadIdx.x] = 0;
}

__global__ void cond_kernel(const float* __restrict__ time_c,
                            const float* __restrict__ ada_w,
                            const float* __restrict__ ada_b) {
    __shared__ float s[DD];
    int b = blockIdx.y;
    for (int i = threadIdx.x; i < DD; i += blockDim.x) {
        float v = time_c[b * DD + i];
        s[i] = v / (1.0f + expf(-v));
    }
    __syncthreads();
    int col = blockIdx.x * 256 + threadIdx.x;
    float acc = 0.0f;
#pragma unroll 4
    for (int r = 0; r < DD; r++) acc += s[r] * ada_w[r * TWOD + col];
    g_cond[b * TWOD + col] = acc + ada_b[col];
}

__global__ void ln_route_kernel(const float* __restrict__ x,
                                const float* __restrict__ gate_w) {
    int tok = blockIdx.x;
    int b = tok / LL;
    const float* xr = x + (size_t)tok * DD;
    __shared__ float sx[DD];
    __shared__ float sred[16];
    __shared__ float smv[2];
    __shared__ float slog[EE];
    int tid = threadIdx.x, lane = tid & 31, w = tid >> 5;
    float lsum = 0.0f, lsq = 0.0f;
    for (int i = tid; i < DD; i += 256) {
        float v = xr[i];
        sx[i] = v; lsum += v; lsq += v * v;
    }
#pragma unroll
    for (int o = 16; o > 0; o >>= 1) {
        lsum += __shfl_down_sync(0xffffffffu, lsum, o);
        lsq  += __shfl_down_sync(0xffffffffu, lsq, o);
    }
    if (lane == 0) { sred[w] = lsum; sred[8 + w] = lsq; }
    __syncthreads();
    if (tid == 0) {
        float s = 0.0f, q = 0.0f;
        for (int i = 0; i < 8; i++) { s += sred[i]; q += sred[8 + i]; }
        float mean = s / (float)DD;
        float var = q / (float)DD - mean * mean;
        smv[0] = mean; smv[1] = rsqrtf(var + EPSV);
    }
    __syncthreads();
    float mean = smv[0], rstd = smv[1];
    const float* shiftp = g_cond + b * TWOD;
    const float* scalep = shiftp + DD;
    for (int i = tid; i < DD; i += 256) {
        float ln = (sx[i] - mean) * rstd;
        float xn = ln * (1.0f + scalep[i]) + shiftp[i];
        sx[i] = xn;
        g_tp[((size_t)(i >> 4) * TT + tok) * 16 + word16(tok, i & 15)] =
            __uint_as_float(f2tf(xn));
    }
    __syncthreads();
    float acc = 0.0f;
    for (int r = lane; r < DD; r += 32) acc += sx[r] * gate_w[r * EE + w];
#pragma unroll
    for (int o = 16; o > 0; o >>= 1) acc += __shfl_down_sync(0xffffffffu, acc, o);
    if (lane == 0) slog[w] = acc;
    __syncthreads();
    if (tid == 0) {
        float m = slog[0];
        for (int e = 1; e < EE; e++) m = fmaxf(m, slog[e]);
        float p[EE];
        for (int e = 0; e < EE; e++) p[e] = expf(slog[e] - m);
        int i0 = 0; float v0 = p[0];
        for (int e = 1; e < EE; e++) if (p[e] > v0) { v0 = p[e]; i0 = e; }
        int i1 = -1; float v1 = -1.0f;
        for (int e = 0; e < EE; e++) if (e != i0 && p[e] > v1) { v1 = p[e]; i1 = e; }
        float inv = 1.0f / (v0 + v1);
        int pos0 = atomicAdd(&g_cnt[i0], 1);
        g_list[i0 * TT + pos0] = tok * 2;
        int pos1 = atomicAdd(&g_cnt[i1], 1);
        g_list[i1 * TT + pos1] = tok * 2 + 1;
        g_pairw[tok * 2] = v0 * inv;
        g_pairw[tok * 2 + 1] = v1 * inv;
    }
}

__global__ void offsets_kernel() {
    if (threadIdx.x == 0) {
        int s = 0;
        for (int e = 0; e < EE; e++) {
            g_off[e] = s;
            g_end[e] = s + g_cnt[e];
            s += (g_cnt[e] + 127) & ~127;      // 128-align each segment
        }
        g_off[EE] = s;
    }
}

__global__ void padinit_kernel() {
    int p = blockIdx.x * 256 + threadIdx.x;
    if (p < RPAD) { g_ptok[p] = 0; g_pw[p] = 0.0f; }
}

__global__ void fill_kernel() {
    int e = blockIdx.x;
    int pos = blockIdx.y * 256 + threadIdx.x;
    if (pos < g_cnt[e]) {
        int pair = g_list[e * TT + pos];
        int p = g_off[e] + pos;
        g_ptok[p] = pair >> 1;
        g_pw[p] = g_pairw[pair];
    }
}

// gather tokens into p-order planes; fix kk-half swizzle for new row index
__global__ void gather_kernel() {
    int id = blockIdx.x * 256 + threadIdx.x;      // RPAD*64 threads
    int p = id >> 6, kt = id & 63;
    int tok = g_ptok[p];
    int swap = ((tok ^ p) >> 1) & 1;
    const float4* s = (const float4*)(g_tp + ((size_t)kt * TT + tok) * 16);
    float4 a = s[0], b = s[1], c = s[2], d = s[3];
    float4* o = (float4*)(g_tr + ((size_t)kt * RPAD + p) * 16);
    if (swap) { o[0] = c; o[1] = d; o[2] = a; o[3] = b; }
    else      { o[0] = a; o[1] = b; o[2] = c; o[3] = d; }
}

// weights [K][N] -> planes [kt][n][16] with word16 layout, tf32-rounded
__global__ void prep_w(const float* __restrict__ W, float* __restrict__ Wp,
                       int Kd, int Nd) {
    __shared__ float s[16][257];
    int e = blockIdx.z;
    const float* w = W + (size_t)e * Kd * Nd;
    float* wp = Wp + (size_t)e * Kd * Nd;
    int kt = blockIdx.y, n0 = blockIdx.x * 256, t = threadIdx.x;
#pragma unroll
    for (int k = 0; k < 16; k++)
        s[k][t] = w[(size_t)(kt * 16 + k) * Nd + n0 + t];
    __syncthreads();
    int n = n0 + t;
    float o[16];
#pragma unroll
    for (int k = 0; k < 16; k++)
        o[word16(n, k)] = __uint_as_float(f2tf(s[k][t]));
    float4* dst = (float4*)(wp + ((size_t)kt * Nd + n) * 16);
    dst[0] = make_float4(o[0], o[1], o[2], o[3]);
    dst[1] = make_float4(o[4], o[5], o[6], o[7]);
    dst[2] = make_float4(o[8], o[9], o[10], o[11]);
    dst[3] = make_float4(o[12], o[13], o[14], o[15]);
}

// ---------------- bulk-copy tf32 mma GEMM ------------------------------------
// C[128x128] = A_planes[rows base..][K] @ W_planes[n0..][K]
template <bool ROUTED, bool FFN2>
__global__ __launch_bounds__(256, 2)
void gemm_blk(const float* __restrict__ Ap, int AR,
              const float* __restrict__ Wpb,
              const float* __restrict__ biasbase,
              const float* __restrict__ xres,
              float* __restrict__ Out, int OutR,
              int Kdim, int Ndim) {
    int e = ROUTED ? blockIdx.z : 0;
    int off0 = ROUTED ? g_off[e] : 0;
    int off1 = ROUTED ? g_end[e] : TT;
    int m0 = blockIdx.y * 128;
    int base = off0 + m0;                  // 128-aligned: word16 row-phase safe
    if (base >= off1) return;
    int n0 = blockIdx.x * 128;
    const float* W = Wpb + (ROUTED ? (size_t)e * Kdim * Ndim : 0);
    const float* bias = biasbase + (ROUTED ? (size_t)e * Ndim : 0);

    extern __shared__ __align__(128) float sm[];
    uint32_t sb = smem_u32(sm);
    int* sorow = (int*)(sm + OFF_META / 4);
    float* swt = (float*)(sorow + 128);
    float* sbias = swt + 128;
    uint32_t mb = sb + OFF_META + 1536;

    int tid = threadIdx.x, wid = tid >> 5, lane = tid & 31;
    if (tid < 128) {
        int row = base + tid;
        bool valid = row < off1;
        int orow; float wv = 1.0f;
        if (!ROUTED) orow = row;
        else if (!FFN2) orow = valid ? row : -1;
        else { orow = valid ? g_ptok[row] : -1; wv = valid ? g_pw[row] : 0.0f; }
        sorow[tid] = orow; swt[tid] = wv; sbias[tid] = bias[n0 + tid];
    }
    if (tid == 0)
        for (int s = 0; s < NSTAGE; s++) MBAR_INIT(mb + 8 * s, 1);
    __syncthreads();

    int NK = Kdim >> 5;                           // 32-K stages
    const float* A0 = Ap + (size_t)base * 16;
    const float* B0 = W + (size_t)n0 * 16;

    if (tid == 0) {
#pragma unroll
        for (int c = 0; c < NSTAGE - 1; c++) {
            uint32_t st = sb + c * STAGE_BYTES;
            EXPECT_TX(mb + 8 * c, 32768u);
            BULK8K(st,          A0 + (size_t)(2 * c) * AR * 16, mb + 8 * c);
            BULK8K(st + 8192,   A0 + (size_t)(2 * c + 1) * AR * 16, mb + 8 * c);
            BULK8K(st + 16384,  B0 + (size_t)(2 * c) * Ndim * 16, mb + 8 * c);
            BULK8K(st + 24576,  B0 + (size_t)(2 * c + 1) * Ndim * 16, mb + 8 * c);
        }
    }

    int wm = wid & 3, wn = wid >> 2, lrow = lane >> 2, lcol = lane & 3;
    int rh = (lrow >> 1) & 1;
    float acc[2][8][4];
#pragma unroll
    for (int a = 0; a < 2; a++)
#pragma unroll
        for (int b = 0; b < 8; b++)
#pragma unroll
            for (int c = 0; c < 4; c++) acc[a][b][c] = 0.0f;

    uint32_t a_off = (uint32_t)((wm * 32 + lrow) * 64 + lcol * 8);
    uint32_t b_off = (uint32_t)(16384 + (wn * 64 + lrow) * 64 + lcol * 8);

    for (int kt = 0; kt < NK; kt++) {
        int slot = kt % NSTAGE;
        MBAR_WAIT(mb + 8 * slot, (kt / NSTAGE) & 1);
        uint32_t st = sb + slot * STAGE_BYTES;
#pragma unroll
        for (int g = 0; g < 4; g++) {
            uint32_t ho = (uint32_t)((((g & 1) ^ rh) << 5));
            uint32_t ab = st + (g >> 1) * 8192 + a_off + ho;
            uint32_t bb = st + (g >> 1) * 8192 + b_off + ho;
            unsigned af[2][4];
#pragma unroll
            for (int tm = 0; tm < 2; tm++) {
                uint32_t p = ab + tm * 1024;
                asm volatile("ld.shared.v2.b32 {%0,%1}, [%2];"
                             : "=r"(af[tm][0]), "=r"(af[tm][2]) : "r"(p));
                asm volatile("ld.shared.v2.b32 {%0,%1}, [%2];"
                             : "=r"(af[tm][1]), "=r"(af[tm][3]) : "r"(p + 512));
            }
            unsigned bf[8][2];
#pragma unroll
            for (int tn = 0; tn < 8; tn++) {
                asm volatile("ld.shared.v2.b32 {%0,%1}, [%2];"
                             : "=r"(bf[tn][0]), "=r"(bf[tn][1])
                             : "r"(bb + tn * 512));
            }
#pragma unroll
            for (int tm = 0; tm < 2; tm++)
#pragma unroll
                for (int tn = 0; tn < 8; tn++)
                    mma_tf32(acc[tm][tn], af[tm], bf[tn]);
        }
        __syncthreads();
        int kl = kt + NSTAGE - 1;
        if (tid == 0 && kl < NK) {
            int sl = kl % NSTAGE;
            uint32_t st2 = sb + sl * STAGE_BYTES;
            EXPECT_TX(mb + 8 * sl, 32768u);
            BULK8K(st2,         A0 + (size_t)(2 * kl) * AR * 16, mb + 8 * sl);
            BULK8K(st2 + 8192,  A0 + (size_t)(2 * kl + 1) * AR * 16, mb + 8 * sl);
            BULK8K(st2 + 16384, B0 + (size_t)(2 * kl) * Ndim * 16, mb + 8 * sl);
            BULK8K(st2 + 24576, B0 + (size_t)(2 * kl + 1) * Ndim * 16, mb + 8 * sl);
        }
    }

    // epilogue
#pragma unroll
    for (int tm = 0; tm < 2; tm++) {
#pragma unroll
        for (int rr = 0; rr < 2; rr++) {
            int li = wm * 32 + tm * 16 + rr * 8 + lrow;
            int orow = sorow[li];
            if (orow < 0) continue;
            float wv = swt[li];
#pragma unroll
            for (int tn = 0; tn < 8; tn++) {
                int c0 = wn * 64 + tn * 8 + lcol * 2;
                float v0 = acc[tm][tn][rr * 2 + 0] + sbias[c0];
                float v1 = acc[tm][tn][rr * 2 + 1] + sbias[c0 + 1];
                if (!FFN2) {
                    int gc = n0 + c0;
                    size_t pbase = ((size_t)(gc >> 4) * OutR + orow) * 16;
                    Out[pbase + word16(orow, gc & 15)] =
                        __uint_as_float(f2tf(geluf(v0)));
                    Out[pbase + word16(orow, (gc + 1) & 15)] =
                        __uint_as_float(f2tf(geluf(v1)));
                } else if (!ROUTED) {
                    size_t o = (size_t)orow * Ndim + n0 + c0;
                    Out[o]     = xres[o]     + v0;
                    Out[o + 1] = xres[o + 1] + v1;
                } else {
                    size_t o = (size_t)orow * Ndim + n0 + c0;
                    atomicAdd(&Out[o],     wv * v0);
                    atomicAdd(&Out[o + 1], wv * v1);
                }
            }
        }
    }
}

// ---------------- launch -----------------------------------------------------
extern "C" void kernel_launch(void* const* d_in, const int* in_sizes, int n_in,
                              void* d_out, int out_size) {
    const float* x      = (const float*)d_in[0];
    const float* time_c = (const float*)d_in[1];
    const float* ada_w  = (const float*)d_in[2];
    const float* ada_b  = (const float*)d_in[3];
    const float* gate_w = (const float*)d_in[4];
    const float* w1     = (const float*)d_in[5];
    const float* b1     = (const float*)d_in[6];
    const float* w2     = (const float*)d_in[7];
    const float* b2     = (const float*)d_in[8];
    const float* sw1    = (const float*)d_in[9];
    const float* sb1    = (const float*)d_in[10];
    const float* sw2    = (const float*)d_in[11];
    const float* sb2    = (const float*)d_in[12];
    float* out = (float*)d_out;

    float *p_tp, *p_tr, *p_hsp, *p_hrp, *p_sw1P, *p_sw2P, *p_w1P, *p_w2P;
    cudaGetSymbolAddress((void**)&p_tp, g_tp);
    cudaGetSymbolAddress((void**)&p_tr, g_tr);
    cudaGetSymbolAddress((void**)&p_hsp, g_hsp);
    cudaGetSymbolAddress((void**)&p_hrp, g_hrp);
    cudaGetSymbolAddress((void**)&p_sw1P, g_sw1P);
    cudaGetSymbolAddress((void**)&p_sw2P, g_sw2P);
    cudaGetSymbolAddress((void**)&p_w1P, g_w1P);
    cudaGetSymbolAddress((void**)&p_w2P, g_w2P);

    cudaFuncSetAttribute(gemm_blk<false, false>,
                         cudaFuncAttributeMaxDynamicSharedMemorySize, SMEM_DYN);
    cudaFuncSetAttribute(gemm_blk<true, false>,
                         cudaFuncAttributeMaxDynamicSharedMemorySize, SMEM_DYN);
    cudaFuncSetAttribute(gemm_blk<false, true>,
                         cudaFuncAttributeMaxDynamicSharedMemorySize, SMEM_DYN);
    cudaFuncSetAttribute(gemm_blk<true, true>,
                         cudaFuncAttributeMaxDynamicSharedMemorySize, SMEM_DYN);

    init_kernel<<<1, 32>>>();
    cond_kernel<<<dim3(TWOD / 256, BB), 256>>>(time_c, ada_w, ada_b);
    ln_route_kernel<<<TT, 256>>>(x, gate_w);
    offsets_kernel<<<1, 32>>>();
    padinit_kernel<<<(RPAD + 255) / 256, 256>>>();
    fill_kernel<<<dim3(EE, TT / 256), 256>>>();
    gather_kernel<<<(RPAD * 64) / 256, 256>>>();

    prep_w<<<dim3(HH / 256, DD / 16, 1), 256>>>(sw1, p_sw1P, DD, HH);
    prep_w<<<dim3(DD / 256, HH / 16, 1), 256>>>(sw2, p_sw2P, HH, DD);
    prep_w<<<dim3(HH / 256, DD / 16, EE), 256>>>(w1, p_w1P, DD, HH);
    prep_w<<<dim3(DD / 256, HH / 16, EE), 256>>>(w2, p_w2P, HH, DD);

    // shared FFN1: hs_planes = tf32(gelu(t @ sw1 + sb1))
    gemm_blk<false, false><<<dim3(HH / 128, TT / 128, 1), 256, SMEM_DYN>>>(
        p_tp, TT, p_sw1P, sb1, nullptr, p_hsp, TT, DD, HH);
    // routed FFN1: hr_planes[p] = tf32(gelu(tr[p] @ w1[e] + b1[e]))
    gemm_blk<true, false><<<dim3(HH / 128, 64, EE), 256, SMEM_DYN>>>(
        p_tr, RPAD, p_w1P, b1, nullptr, p_hrp, RPAD, DD, HH);
    // shared FFN2 (+residual init): out = x + hs @ sw2 + sb2
    gemm_blk<false, true><<<dim3(DD / 128, TT / 128, 1), 256, SMEM_DYN>>>(
        p_hsp, TT, p_sw2P, sb2, x, out, 0, HH, DD);
    // routed FFN2: out[tok] += w * (hr[p] @ w2[e] + b2[e])
    gemm_blk<true, true><<<dim3(DD / 128, 64, EE), 256, SMEM_DYN>>>(
        p_hrp, RPAD, p_w2P, b2, nullptr, out, 0, HH, DD);
}

// round 14
// speedup vs baseline: 1.5395x; 1.0968x over previous
#include <cuda_runtime.h>
#include <math.h>
#include <stdint.h>

// Problem constants
#define BB 4
#define LL 2048
#define DD 1024
#define EE 8
#define HH 4096
#define TT 8192
#define TWOD 2048
#define EPSV 1e-6f
#define RPAD 17536              // padded routed rows (128-aligned expert segments)

// GEMM: CTA 128M x 128N, stage = 32 K (two 16-k planes), 3 stages
// 4 warps of 64x64, 2 CTAs/SM
#define STAGE_BYTES 32768
#define NSTAGE 3
#define OFF_META (NSTAGE * STAGE_BYTES)          // 98304
#define SMEM_DYN (OFF_META + 2048)               // 100352 bytes

// ---------------- device scratch ---------------------------------------------
__device__ float g_cond[BB * TWOD];
__device__ float g_tp[(size_t)64 * TT * 16];          // xn tokens, plane layout
__device__ float g_tr[(size_t)64 * RPAD * 16];        // gathered tokens (p-order)
__device__ float g_hsp[(size_t)256 * TT * 16];        // shared hidden planes
__device__ float g_hrp[(size_t)256 * RPAD * 16];      // routed hidden planes
__device__ float g_sw1P[(size_t)64 * HH * 16];
__device__ float g_sw2P[(size_t)256 * DD * 16];
__device__ float g_w1P[(size_t)EE * 64 * HH * 16];
__device__ float g_w2P[(size_t)EE * 256 * DD * 16];
__device__ int   g_cnt[EE];
__device__ int   g_off[EE + 1];                       // 128-aligned starts
__device__ int   g_end[EE];                           // true ends
__device__ int   g_list[EE * TT];
__device__ float g_pairw[2 * TT];
__device__ int   g_ptok[RPAD];
__device__ float g_pw[RPAD];

// ---------------- helpers ----------------------------------------------------
__device__ __forceinline__ unsigned f2tf(float f) {
    unsigned u;
    asm("cvt.rna.tf32.f32 %0, %1;" : "=r"(u) : "f"(f));
    return u;
}

__device__ __forceinline__ float geluf(float v) {
    float u = 0.7978845608028654f * (v + 0.044715f * v * v * v);
    return 0.5f * v * (1.0f + tanhf(u));
}

__device__ __forceinline__ uint32_t smem_u32(const void* p) {
    uint32_t a;
    asm("{ .reg .u64 t; cvta.to.shared.u64 t, %1; cvt.u32.u64 %0, t; }"
        : "=r"(a) : "l"(p));
    return a;
}

// word index (0..15) of logical k (0..15) within a 64B plane-row of row r.
// pairs (k, k+4) adjacent; kk-halves swapped by row bit1 for bank spread.
// NOTE: row-dependent (bit1 of r) — all tile bases must be 128-aligned so the
// consumer's tile-local row is congruent to the producer's global row mod 4.
__device__ __forceinline__ int word16(int r, int k) {
    int pos = (k & 8) | ((k & 3) << 1) | ((k >> 2) & 1);
    return ((((pos >> 3) ^ (r >> 1)) & 1) << 3) | (pos & 7);
}

__device__ __forceinline__ void mma_tf32(float* c, const unsigned* a, const unsigned* b) {
    asm volatile(
        "mma.sync.aligned.m16n8k8.row.col.f32.tf32.tf32.f32 "
        "{%0,%1,%2,%3}, {%4,%5,%6,%7}, {%8,%9}, {%0,%1,%2,%3};\n"
        : "+f"(c[0]), "+f"(c[1]), "+f"(c[2]), "+f"(c[3])
        : "r"(a[0]), "r"(a[1]), "r"(a[2]), "r"(a[3]), "r"(b[0]), "r"(b[1]));
}

#define MBAR_INIT(a, cnt) \
    asm volatile("mbarrier.init.shared.b64 [%0], %1;" :: "r"(a), "r"(cnt) : "memory")

#define EXPECT_TX(mbar, n) \
    asm volatile("mbarrier.arrive.expect_tx.shared.b64 _, [%0], %1;" \
                 :: "r"(mbar), "r"(n) : "memory")

#define BULK8K(dst, src, mbar) \
    asm volatile("cp.async.bulk.shared::cluster.global.mbarrier::complete_tx::bytes " \
                 "[%0], [%1], %2, [%3];" \
                 :: "r"(dst), "l"(src), "r"(8192u), "r"(mbar) : "memory")

#define MBAR_WAIT(mbar, par) do {                                              \
    uint32_t _m = (mbar); uint32_t _p = (par); uint32_t _d;                    \
    asm volatile("{\n\t.reg .pred p;\n\t"                                      \
        "mbarrier.try_wait.parity.acquire.cta.shared::cta.b64 p, [%1], %2;\n\t"\
        "selp.b32 %0, 1, 0, p;\n\t}" : "=r"(_d) : "r"(_m), "r"(_p) : "memory");\
    if (!_d) {                                                                 \
        asm volatile("{\n\t.reg .pred P1;\n\t"                                 \
            "W0_%=:\n\t"                                                       \
            "mbarrier.try_wait.parity.acquire.cta.shared::cta.b64 P1, [%0], %1, 0x989680;\n\t" \
            "@P1 bra.uni W1_%=;\n\t"                                           \
            "bra.uni W0_%=;\n\t"                                               \
            "W1_%=:\n\t}" :: "r"(_m), "r"(_p) : "memory");                     \
    }                                                                          \
} while (0)

// ---------------- small kernels ----------------------------------------------
__global__ void init_kernel() {
    if (threadIdx.x < EE) g_cnt[threadIdx.x] = 0;
}

__global__ void cond_kernel(const float* __restrict__ time_c,
                            const float* __restrict__ ada_w,
                            const float* __restrict__ ada_b) {
    __shared__ float s[DD];
    int b = blockIdx.y;
    for (int i = threadIdx.x; i < DD; i += blockDim.x) {
        float v = time_c[b * DD + i];
        s[i] = v / (1.0f + expf(-v));
    }
    __syncthreads();
    int col = blockIdx.x * 256 + threadIdx.x;
    float acc = 0.0f;
#pragma unroll 4
    for (int r = 0; r < DD; r++) acc += s[r] * ada_w[r * TWOD + col];
    g_cond[b * TWOD + col] = acc + ada_b[col];
}

__global__ void ln_route_kernel(const float* __restrict__ x,
                                const float* __restrict__ gate_w) {
    int tok = blockIdx.x;
    int b = tok / LL;
    const float* xr = x + (size_t)tok * DD;
    __shared__ float sx[DD];
    __shared__ float sred[16];
    __shared__ float smv[2];
    __shared__ float slog[EE];
    int tid = threadIdx.x, lane = tid & 31, w = tid >> 5;
    float lsum = 0.0f, lsq = 0.0f;
    for (int i = tid; i < DD; i += 256) {
        float v = xr[i];
        sx[i] = v; lsum += v; lsq += v * v;
    }
#pragma unroll
    for (int o = 16; o > 0; o >>= 1) {
        lsum += __shfl_down_sync(0xffffffffu, lsum, o);
        lsq  += __shfl_down_sync(0xffffffffu, lsq, o);
    }
    if (lane == 0) { sred[w] = lsum; sred[8 + w] = lsq; }
    __syncthreads();
    if (tid == 0) {
        float s = 0.0f, q = 0.0f;
        for (int i = 0; i < 8; i++) { s += sred[i]; q += sred[8 + i]; }
        float mean = s / (float)DD;
        float var = q / (float)DD - mean * mean;
        smv[0] = mean; smv[1] = rsqrtf(var + EPSV);
    }
    __syncthreads();
    float mean = smv[0], rstd = smv[1];
    const float* shiftp = g_cond + b * TWOD;
    const float* scalep = shiftp + DD;
    for (int i = tid; i < DD; i += 256) {
        float ln = (sx[i] - mean) * rstd;
        float xn = ln * (1.0f + scalep[i]) + shiftp[i];
        sx[i] = xn;
        g_tp[((size_t)(i >> 4) * TT + tok) * 16 + word16(tok, i & 15)] =
            __uint_as_float(f2tf(xn));
    }
    __syncthreads();
    float acc = 0.0f;
    for (int r = lane; r < DD; r += 32) acc += sx[r] * gate_w[r * EE + w];
#pragma unroll
    for (int o = 16; o > 0; o >>= 1) acc += __shfl_down_sync(0xffffffffu, acc, o);
    if (lane == 0) slog[w] = acc;
    __syncthreads();
    if (tid == 0) {
        float m = slog[0];
        for (int e = 1; e < EE; e++) m = fmaxf(m, slog[e]);
        float p[EE];
        for (int e = 0; e < EE; e++) p[e] = expf(slog[e] - m);
        int i0 = 0; float v0 = p[0];
        for (int e = 1; e < EE; e++) if (p[e] > v0) { v0 = p[e]; i0 = e; }
        int i1 = -1; float v1 = -1.0f;
        for (int e = 0; e < EE; e++) if (e != i0 && p[e] > v1) { v1 = p[e]; i1 = e; }
        float inv = 1.0f / (v0 + v1);
        int pos0 = atomicAdd(&g_cnt[i0], 1);
        g_list[i0 * TT + pos0] = tok * 2;
        int pos1 = atomicAdd(&g_cnt[i1], 1);
        g_list[i1 * TT + pos1] = tok * 2 + 1;
        g_pairw[tok * 2] = v0 * inv;
        g_pairw[tok * 2 + 1] = v1 * inv;
    }
}

__global__ void offsets_kernel() {
    if (threadIdx.x == 0) {
        int s = 0;
        for (int e = 0; e < EE; e++) {
            g_off[e] = s;
            g_end[e] = s + g_cnt[e];
            s += (g_cnt[e] + 127) & ~127;      // 128-align each segment
        }
        g_off[EE] = s;
    }
}

__global__ void padinit_kernel() {
    int p = blockIdx.x * 256 + threadIdx.x;
    if (p < RPAD) { g_ptok[p] = 0; g_pw[p] = 0.0f; }
}

__global__ void fill_kernel() {
    int e = blockIdx.x;
    int pos = blockIdx.y * 256 + threadIdx.x;
    if (pos < g_cnt[e]) {
        int pair = g_list[e * TT + pos];
        int p = g_off[e] + pos;
        g_ptok[p] = pair >> 1;
        g_pw[p] = g_pairw[pair];
    }
}

// gather tokens into p-order planes; fix kk-half swizzle for new row index
__global__ void gather_kernel() {
    int id = blockIdx.x * 256 + threadIdx.x;      // RPAD*64 threads
    int p = id >> 6, kt = id & 63;
    int tok = g_ptok[p];
    int swap = ((tok ^ p) >> 1) & 1;
    const float4* s = (const float4*)(g_tp + ((size_t)kt * TT + tok) * 16);
    float4 a = s[0], b = s[1], c = s[2], d = s[3];
    float4* o = (float4*)(g_tr + ((size_t)kt * RPAD + p) * 16);
    if (swap) { o[0] = c; o[1] = d; o[2] = a; o[3] = b; }
    else      { o[0] = a; o[1] = b; o[2] = c; o[3] = d; }
}

// weights [K][N] -> planes [kt][n][16] with word16 layout, tf32-rounded
__global__ void prep_w(const float* __restrict__ W, float* __restrict__ Wp,
                       int Kd, int Nd) {
    __shared__ float s[16][257];
    int e = blockIdx.z;
    const float* w = W + (size_t)e * Kd * Nd;
    float* wp = Wp + (size_t)e * Kd * Nd;
    int kt = blockIdx.y, n0 = blockIdx.x * 256, t = threadIdx.x;
#pragma unroll
    for (int k = 0; k < 16; k++)
        s[k][t] = w[(size_t)(kt * 16 + k) * Nd + n0 + t];
    __syncthreads();
    int n = n0 + t;
    float o[16];
#pragma unroll
    for (int k = 0; k < 16; k++)
        o[word16(n, k)] = __uint_as_float(f2tf(s[k][t]));
    float4* dst = (float4*)(wp + ((size_t)kt * Nd + n) * 16);
    dst[0] = make_float4(o[0], o[1], o[2], o[3]);
    dst[1] = make_float4(o[4], o[5], o[6], o[7]);
    dst[2] = make_float4(o[8], o[9], o[10], o[11]);
    dst[3] = make_float4(o[12], o[13], o[14], o[15]);
}

// ---------------- bulk-copy tf32 mma GEMM (4 warps of 64x64) ------------------
// C[128x128] = A_planes[rows base..][K] @ W_planes[n0..][K]
template <bool ROUTED, bool FFN2>
__global__ __launch_bounds__(128, 2)
void gemm_blk(const float* __restrict__ Ap, int AR,
              const float* __restrict__ Wpb,
              const float* __restrict__ biasbase,
              const float* __restrict__ xres,
              float* __restrict__ Out, int OutR,
              int Kdim, int Ndim) {
    int e = ROUTED ? blockIdx.z : 0;
    int off0 = ROUTED ? g_off[e] : 0;
    int off1 = ROUTED ? g_end[e] : TT;
    int m0 = blockIdx.y * 128;
    int base = off0 + m0;                  // 128-aligned: word16 row-phase safe
    if (base >= off1) return;
    int n0 = blockIdx.x * 128;
    const float* W = Wpb + (ROUTED ? (size_t)e * Kdim * Ndim : 0);
    const float* bias = biasbase + (ROUTED ? (size_t)e * Ndim : 0);

    extern __shared__ __align__(128) float sm[];
    uint32_t sb = smem_u32(sm);
    int* sorow = (int*)(sm + OFF_META / 4);
    float* swt = (float*)(sorow + 128);
    float* sbias = swt + 128;
    uint32_t mb = sb + OFF_META + 1536;

    int tid = threadIdx.x, wid = tid >> 5, lane = tid & 31;
    {   // all 128 threads stage metadata
        int row = base + tid;
        bool valid = row < off1;
        int orow; float wv = 1.0f;
        if (!ROUTED) orow = row;
        else if (!FFN2) orow = valid ? row : -1;
        else { orow = valid ? g_ptok[row] : -1; wv = valid ? g_pw[row] : 0.0f; }
        sorow[tid] = orow; swt[tid] = wv; sbias[tid] = bias[n0 + tid];
    }
    if (tid == 0)
        for (int s = 0; s < NSTAGE; s++) MBAR_INIT(mb + 8 * s, 1);
    __syncthreads();

    int NK = Kdim >> 5;                           // 32-K stages
    const float* A0 = Ap + (size_t)base * 16;
    const float* B0 = W + (size_t)n0 * 16;

    if (tid == 0) {
#pragma unroll
        for (int c = 0; c < NSTAGE - 1; c++) {
            uint32_t st = sb + c * STAGE_BYTES;
            EXPECT_TX(mb + 8 * c, 32768u);
            BULK8K(st,          A0 + (size_t)(2 * c) * AR * 16, mb + 8 * c);
            BULK8K(st + 8192,   A0 + (size_t)(2 * c + 1) * AR * 16, mb + 8 * c);
            BULK8K(st + 16384,  B0 + (size_t)(2 * c) * Ndim * 16, mb + 8 * c);
            BULK8K(st + 24576,  B0 + (size_t)(2 * c + 1) * Ndim * 16, mb + 8 * c);
        }
    }

    // 4 warps in 2x2: warp tile 64M x 64N
    int wm = wid & 1, wn = wid >> 1, lrow = lane >> 2, lcol = lane & 3;
    int rh = (lrow >> 1) & 1;
    float acc[4][8][4];
#pragma unroll
    for (int a = 0; a < 4; a++)
#pragma unroll
        for (int b = 0; b < 8; b++)
#pragma unroll
            for (int c = 0; c < 4; c++) acc[a][b][c] = 0.0f;

    uint32_t a_off = (uint32_t)((wm * 64 + lrow) * 64 + lcol * 8);
    uint32_t b_off = (uint32_t)(16384 + (wn * 64 + lrow) * 64 + lcol * 8);

    for (int kt = 0; kt < NK; kt++) {
        int slot = kt % NSTAGE;
        MBAR_WAIT(mb + 8 * slot, (kt / NSTAGE) & 1);
        uint32_t st = sb + slot * STAGE_BYTES;
#pragma unroll
        for (int g = 0; g < 4; g++) {
            uint32_t ho = (uint32_t)((((g & 1) ^ rh) << 5));
            uint32_t ab = st + (g >> 1) * 8192 + a_off + ho;
            uint32_t bb = st + (g >> 1) * 8192 + b_off + ho;
            unsigned af[4][4];
#pragma unroll
            for (int tm = 0; tm < 4; tm++) {
                uint32_t p = ab + tm * 1024;           // tm*16 rows * 64B
                asm volatile("ld.shared.v2.b32 {%0,%1}, [%2];"
                             : "=r"(af[tm][0]), "=r"(af[tm][2]) : "r"(p));
                asm volatile("ld.shared.v2.b32 {%0,%1}, [%2];"
                             : "=r"(af[tm][1]), "=r"(af[tm][3]) : "r"(p + 512));
            }
            unsigned bf[8][2];
#pragma unroll
            for (int tn = 0; tn < 8; tn++) {
                asm volatile("ld.shared.v2.b32 {%0,%1}, [%2];"
                             : "=r"(bf[tn][0]), "=r"(bf[tn][1])
                             : "r"(bb + tn * 512));
            }
#pragma unroll
            for (int tm = 0; tm < 4; tm++)
#pragma unroll
                for (int tn = 0; tn < 8; tn++)
                    mma_tf32(acc[tm][tn], af[tm], bf[tn]);
        }
        __syncthreads();
        int kl = kt + NSTAGE - 1;
        if (tid == 0 && kl < NK) {
            int sl = kl % NSTAGE;
            uint32_t st2 = sb + sl * STAGE_BYTES;
            EXPECT_TX(mb + 8 * sl, 32768u);
            BULK8K(st2,         A0 + (size_t)(2 * kl) * AR * 16, mb + 8 * sl);
            BULK8K(st2 + 8192,  A0 + (size_t)(2 * kl + 1) * AR * 16, mb + 8 * sl);
            BULK8K(st2 + 16384, B0 + (size_t)(2 * kl) * Ndim * 16, mb + 8 * sl);
            BULK8K(st2 + 24576, B0 + (size_t)(2 * kl + 1) * Ndim * 16, mb + 8 * sl);
        }
    }

    // epilogue
#pragma unroll
    for (int tm = 0; tm < 4; tm++) {
#pragma unroll
        for (int rr = 0; rr < 2; rr++) {
            int li = wm * 64 + tm * 16 + rr * 8 + lrow;
            int orow = sorow[li];
            if (orow < 0) continue;
            float wv = swt[li];
#pragma unroll
            for (int tn = 0; tn < 8; tn++) {
                int c0 = wn * 64 + tn * 8 + lcol * 2;
                float v0 = acc[tm][tn][rr * 2 + 0] + sbias[c0];
                float v1 = acc[tm][tn][rr * 2 + 1] + sbias[c0 + 1];
                if (!FFN2) {
                    int gc = n0 + c0;
                    size_t pbase = ((size_t)(gc >> 4) * OutR + orow) * 16;
                    Out[pbase + word16(orow, gc & 15)] =
                        __uint_as_float(f2tf(geluf(v0)));
                    Out[pbase + word16(orow, (gc + 1) & 15)] =
                        __uint_as_float(f2tf(geluf(v1)));
                } else if (!ROUTED) {
                    size_t o = (size_t)orow * Ndim + n0 + c0;
                    Out[o]     = xres[o]     + v0;
                    Out[o + 1] = xres[o + 1] + v1;
                } else {
                    size_t o = (size_t)orow * Ndim + n0 + c0;
                    atomicAdd(&Out[o],     wv * v0);
                    atomicAdd(&Out[o + 1], wv * v1);
                }
            }
        }
    }
}

// ---------------- launch -----------------------------------------------------
extern "C" void kernel_launch(void* const* d_in, const int* in_sizes, int n_in,
                              void* d_out, int out_size) {
    const float* x      = (const float*)d_in[0];
    const float* time_c = (const float*)d_in[1];
    const float* ada_w  = (const float*)d_in[2];
    const float* ada_b  = (const float*)d_in[3];
    const float* gate_w = (const float*)d_in[4];
    const float* w1     = (const float*)d_in[5];
    const float* b1     = (const float*)d_in[6];
    const float* w2     = (const float*)d_in[7];
    const float* b2     = (const float*)d_in[8];
    const float* sw1    = (const float*)d_in[9];
    const float* sb1    = (const float*)d_in[10];
    const float* sw2    = (const float*)d_in[11];
    const float* sb2    = (const float*)d_in[12];
    float* out = (float*)d_out;

    float *p_tp, *p_tr, *p_hsp, *p_hrp, *p_sw1P, *p_sw2P, *p_w1P, *p_w2P;
    cudaGetSymbolAddress((void**)&p_tp, g_tp);
    cudaGetSymbolAddress((void**)&p_tr, g_tr);
    cudaGetSymbolAddress((void**)&p_hsp, g_hsp);
    cudaGetSymbolAddress((void**)&p_hrp, g_hrp);
    cudaGetSymbolAddress((void**)&p_sw1P, g_sw1P);
    cudaGetSymbolAddress((void**)&p_sw2P, g_sw2P);
    cudaGetSymbolAddress((void**)&p_w1P, g_w1P);
    cudaGetSymbolAddress((void**)&p_w2P, g_w2P);

    cudaFuncSetAttribute(gemm_blk<false, false>,
                         cudaFuncAttributeMaxDynamicSharedMemorySize, SMEM_DYN);
    cudaFuncSetAttribute(gemm_blk<true, false>,
                         cudaFuncAttributeMaxDynamicSharedMemorySize, SMEM_DYN);
    cudaFuncSetAttribute(gemm_blk<false, true>,
                         cudaFuncAttributeMaxDynamicSharedMemorySize, SMEM_DYN);
    cudaFuncSetAttribute(gemm_blk<true, true>,
                         cudaFuncAttributeMaxDynamicSharedMemorySize, SMEM_DYN);

    init_kernel<<<1, 32>>>();
    cond_kernel<<<dim3(TWOD / 256, BB), 256>>>(time_c, ada_w, ada_b);
    ln_route_kernel<<<TT, 256>>>(x, gate_w);
    offsets_kernel<<<1, 32>>>();
    padinit_kernel<<<(RPAD + 255) / 256, 256>>>();
    fill_kernel<<<dim3(EE, TT / 256), 256>>>();
    gather_kernel<<<(RPAD * 64) / 256, 256>>>();

    prep_w<<<dim3(HH / 256, DD / 16, 1), 256>>>(sw1, p_sw1P, DD, HH);
    prep_w<<<dim3(DD / 256, HH / 16, 1), 256>>>(sw2, p_sw2P, HH, DD);
    prep_w<<<dim3(HH / 256, DD / 16, EE), 256>>>(w1, p_w1P, DD, HH);
    prep_w<<<dim3(DD / 256, HH / 16, EE), 256>>>(w2, p_w2P, HH, DD);

    // shared FFN1: hs_planes = tf32(gelu(t @ sw1 + sb1))
    gemm_blk<false, false><<<dim3(HH / 128, TT / 128, 1), 128, SMEM_DYN>>>(
        p_tp, TT, p_sw1P, sb1, nullptr, p_hsp, TT, DD, HH);
    // routed FFN1: hr_planes[p] = tf32(gelu(tr[p] @ w1[e] + b1[e]))
    gemm_blk<true, false><<<dim3(HH / 128, 64, EE), 128, SMEM_DYN>>>(
        p_tr, RPAD, p_w1P, b1, nullptr, p_hrp, RPAD, DD, HH);
    // shared FFN2 (+residual init): out = x + hs @ sw2 + sb2
    gemm_blk<false, true><<<dim3(DD / 128, TT / 128, 1), 128, SMEM_DYN>>>(
        p_hsp, TT, p_sw2P, sb2, x, out, 0, HH, DD);
    // routed FFN2: out[tok] += w * (hr[p] @ w2[e] + b2[e])
    gemm_blk<true, true><<<dim3(DD / 128, 64, EE), 128, SMEM_DYN>>>(
        p_hrp, RPAD, p_w2P, b2, nullptr, out, 0, HH, DD);
}

// round 15
// speedup vs baseline: 2.6033x; 1.6910x over previous
#include <cuda_runtime.h>
#include <cuda_fp16.h>
#include <math.h>
#include <stdint.h>

// Problem constants
#define BB 4
#define LL 2048
#define DD 1024
#define EE 8
#define HH 4096
#define TT 8192
#define TWOD 2048
#define EPSV 1e-6f
#define RPAD 17536              // padded routed rows (128-aligned expert segments)

// GEMM: CTA 128M x 128N, fp16 mma m16n8k16.
// stage = 64 K (two 32-k fp16 planes per operand), 32KB/stage, 3 stages.
// 4 warps of 64x64, 2 CTAs/SM.
#define STAGE_BYTES 32768
#define NSTAGE 3
#define OFF_META (NSTAGE * STAGE_BYTES)          // 98304
#define SMEM_DYN (OFF_META + 2048)               // 100352 bytes

// ---------------- device scratch ---------------------------------------------
__device__ float  g_cond[BB * TWOD];
__device__ __half g_tph[(size_t)32 * TT * 32];        // xn tokens, fp16 planes
__device__ __half g_trh[(size_t)32 * RPAD * 32];      // gathered tokens (p-order)
__device__ __half g_hsph[(size_t)128 * TT * 32];      // shared hidden planes
__device__ __half g_hrph[(size_t)128 * RPAD * 32];    // routed hidden planes
__device__ __half g_sw1P[(size_t)32 * HH * 32];
__device__ __half g_sw2P[(size_t)128 * DD * 32];
__device__ __half g_w1P[(size_t)EE * 32 * HH * 32];
__device__ __half g_w2P[(size_t)EE * 128 * DD * 32];
__device__ int    g_cnt[EE];
__device__ int    g_off[EE + 1];                      // 128-aligned starts
__device__ int    g_end[EE];                          // true ends
__device__ int    g_list[EE * TT];
__device__ float  g_pairw[2 * TT];
__device__ int    g_ptok[RPAD];
__device__ float  g_pw[RPAD];

// ---------------- helpers ----------------------------------------------------
__device__ __forceinline__ float geluf(float v) {
    float u = 0.7978845608028654f * (v + 0.044715f * v * v * v);
    return 0.5f * v * (1.0f + tanhf(u));
}

__device__ __forceinline__ uint32_t smem_u32(const void* p) {
    uint32_t a;
    asm("{ .reg .u64 t; cvta.to.shared.u64 t, %1; cvt.u32.u64 %0, t; }"
        : "=r"(a) : "l"(p));
    return a;
}

// fp16 plane row = 32 halves (64B) covering 32 k values = two k16 groups.
// Each 32B half-group holds 8 k-pairs at slot order [0,4,1,5,2,6,3,7];
// half-groups are swapped by bit1 of the row index (bank spread).
// half-index (0..31) of logical k (0..31) within the row of row-index r:
__device__ __forceinline__ int hidx32(int r, int k) {
    int g = (k >> 4) & 1;
    int j = (k >> 1) & 7;
    int slot = ((j & 3) << 1) | (j >> 2);
    int h = g ^ ((r >> 1) & 1);
    return h * 16 + slot * 2 + (k & 1);
}

__device__ __forceinline__ void mma_f16(float* c, const unsigned* a, const unsigned* b) {
    asm volatile(
        "mma.sync.aligned.m16n8k16.row.col.f32.f16.f16.f32 "
        "{%0,%1,%2,%3}, {%4,%5,%6,%7}, {%8,%9}, {%0,%1,%2,%3};\n"
        : "+f"(c[0]), "+f"(c[1]), "+f"(c[2]), "+f"(c[3])
        : "r"(a[0]), "r"(a[1]), "r"(a[2]), "r"(a[3]), "r"(b[0]), "r"(b[1]));
}

#define MBAR_INIT(a, cnt) \
    asm volatile("mbarrier.init.shared.b64 [%0], %1;" :: "r"(a), "r"(cnt) : "memory")

#define EXPECT_TX(mbar, n) \
    asm volatile("mbarrier.arrive.expect_tx.shared.b64 _, [%0], %1;" \
                 :: "r"(mbar), "r"(n) : "memory")

#define BULK8K(dst, src, mbar) \
    asm volatile("cp.async.bulk.shared::cluster.global.mbarrier::complete_tx::bytes " \
                 "[%0], [%1], %2, [%3];" \
                 :: "r"(dst), "l"(src), "r"(8192u), "r"(mbar) : "memory")

#define MBAR_WAIT(mbar, par) do {                                              \
    uint32_t _m = (mbar); uint32_t _p = (par); uint32_t _d;                    \
    asm volatile("{\n\t.reg .pred p;\n\t"                                      \
        "mbarrier.try_wait.parity.acquire.cta.shared::cta.b64 p, [%1], %2;\n\t"\
        "selp.b32 %0, 1, 0, p;\n\t}" : "=r"(_d) : "r"(_m), "r"(_p) : "memory");\
    if (!_d) {                                                                 \
        asm volatile("{\n\t.reg .pred P1;\n\t"                                 \
            "W0_%=:\n\t"                                                       \
            "mbarrier.try_wait.parity.acquire.cta.shared::cta.b64 P1, [%0], %1, 0x989680;\n\t" \
            "@P1 bra.uni W1_%=;\n\t"                                           \
            "bra.uni W0_%=;\n\t"                                               \
            "W1_%=:\n\t}" :: "r"(_m), "r"(_p) : "memory");                     \
    }                                                                          \
} while (0)

// ---------------- small kernels ----------------------------------------------
__global__ void init_kernel() {
    if (threadIdx.x < EE) g_cnt[threadIdx.x] = 0;
}

__global__ void cond_kernel(const float* __restrict__ time_c,
                            const float* __restrict__ ada_w,
                            const float* __restrict__ ada_b) {
    __shared__ float s[DD];
    int b = blockIdx.y;
    for (int i = threadIdx.x; i < DD; i += blockDim.x) {
        float v = time_c[b * DD + i];
        s[i] = v / (1.0f + expf(-v));
    }
    __syncthreads();
    int col = blockIdx.x * 256 + threadIdx.x;
    float acc = 0.0f;
#pragma unroll 4
    for (int r = 0; r < DD; r++) acc += s[r] * ada_w[r * TWOD + col];
    g_cond[b * TWOD + col] = acc + ada_b[col];
}

__global__ void ln_route_kernel(const float* __restrict__ x,
                                const float* __restrict__ gate_w) {
    int tok = blockIdx.x;
    int b = tok / LL;
    const float* xr = x + (size_t)tok * DD;
    __shared__ float sx[DD];
    __shared__ float sred[16];
    __shared__ float smv[2];
    __shared__ float slog[EE];
    int tid = threadIdx.x, lane = tid & 31, w = tid >> 5;
    float lsum = 0.0f, lsq = 0.0f;
    for (int i = tid; i < DD; i += 256) {
        float v = xr[i];
        sx[i] = v; lsum += v; lsq += v * v;
    }
#pragma unroll
    for (int o = 16; o > 0; o >>= 1) {
        lsum += __shfl_down_sync(0xffffffffu, lsum, o);
        lsq  += __shfl_down_sync(0xffffffffu, lsq, o);
    }
    if (lane == 0) { sred[w] = lsum; sred[8 + w] = lsq; }
    __syncthreads();
    if (tid == 0) {
        float s = 0.0f, q = 0.0f;
        for (int i = 0; i < 8; i++) { s += sred[i]; q += sred[8 + i]; }
        float mean = s / (float)DD;
        float var = q / (float)DD - mean * mean;
        smv[0] = mean; smv[1] = rsqrtf(var + EPSV);
    }
    __syncthreads();
    float mean = smv[0], rstd = smv[1];
    const float* shiftp = g_cond + b * TWOD;
    const float* scalep = shiftp + DD;
    for (int i = tid; i < DD; i += 256) {
        float ln = (sx[i] - mean) * rstd;
        float xn = ln * (1.0f + scalep[i]) + shiftp[i];
        sx[i] = xn;
        g_tph[((size_t)(i >> 5) * TT + tok) * 32 + hidx32(tok, i & 31)] =
            __float2half_rn(xn);
    }
    __syncthreads();
    float acc = 0.0f;
    for (int r = lane; r < DD; r += 32) acc += sx[r] * gate_w[r * EE + w];
#pragma unroll
    for (int o = 16; o > 0; o >>= 1) acc += __shfl_down_sync(0xffffffffu, acc, o);
    if (lane == 0) slog[w] = acc;
    __syncthreads();
    if (tid == 0) {
        float m = slog[0];
        for (int e = 1; e < EE; e++) m = fmaxf(m, slog[e]);
        float p[EE];
        for (int e = 0; e < EE; e++) p[e] = expf(slog[e] - m);
        int i0 = 0; float v0 = p[0];
        for (int e = 1; e < EE; e++) if (p[e] > v0) { v0 = p[e]; i0 = e; }
        int i1 = -1; float v1 = -1.0f;
        for (int e = 0; e < EE; e++) if (e != i0 && p[e] > v1) { v1 = p[e]; i1 = e; }
        float inv = 1.0f / (v0 + v1);
        int pos0 = atomicAdd(&g_cnt[i0], 1);
        g_list[i0 * TT + pos0] = tok * 2;
        int pos1 = atomicAdd(&g_cnt[i1], 1);
        g_list[i1 * TT + pos1] = tok * 2 + 1;
        g_pairw[tok * 2] = v0 * inv;
        g_pairw[tok * 2 + 1] = v1 * inv;
    }
}

__global__ void offsets_kernel() {
    if (threadIdx.x == 0) {
        int s = 0;
        for (int e = 0; e < EE; e++) {
            g_off[e] = s;
            g_end[e] = s + g_cnt[e];
            s += (g_cnt[e] + 127) & ~127;      // 128-align each segment
        }
        g_off[EE] = s;
    }
}

__global__ void padinit_kernel() {
    int p = blockIdx.x * 256 + threadIdx.x;
    if (p < RPAD) { g_ptok[p] = 0; g_pw[p] = 0.0f; }
}

__global__ void fill_kernel() {
    int e = blockIdx.x;
    int pos = blockIdx.y * 256 + threadIdx.x;
    if (pos < g_cnt[e]) {
        int pair = g_list[e * TT + pos];
        int p = g_off[e] + pos;
        g_ptok[p] = pair >> 1;
        g_pw[p] = g_pairw[pair];
    }
}

// gather tokens into p-order planes; fix bit1 half-swap for new row index
__global__ void gather_kernel() {
    int id = blockIdx.x * 256 + threadIdx.x;      // RPAD*32 threads
    int p = id >> 5, kt = id & 31;
    int tok = g_ptok[p];
    int swap = ((tok ^ p) >> 1) & 1;
    const uint4* s = (const uint4*)(g_trh + 0, g_tph + ((size_t)kt * TT + tok) * 32);
    uint4 a = s[0], b = s[1], c = s[2], d = s[3];
    uint4* o = (uint4*)(g_trh + ((size_t)kt * RPAD + p) * 32);
    if (swap) { o[0] = c; o[1] = d; o[2] = a; o[3] = b; }
    else      { o[0] = a; o[1] = b; o[2] = c; o[3] = d; }
}

// weights [K][N] -> fp16 planes [kt32][n][32] with hidx32 layout
__global__ void prep_w(const float* __restrict__ W, __half* __restrict__ Wp,
                       int Kd, int Nd) {
    __shared__ float s[32][257];
    int e = blockIdx.z;
    const float* w = W + (size_t)e * Kd * Nd;
    __half* wp = Wp + (size_t)e * Kd * Nd;
    int kt = blockIdx.y, n0 = blockIdx.x * 256, t = threadIdx.x;
#pragma unroll
    for (int k = 0; k < 32; k++)
        s[k][t] = w[(size_t)(kt * 32 + k) * Nd + n0 + t];
    __syncthreads();
    int n = n0 + t;
    unsigned words[16];
#pragma unroll
    for (int wo = 0; wo < 16; wo++) {
        int h = wo >> 3;                 // half-group
        int slot = wo & 7;
        int j = ((slot >> 1) & 3) | ((slot & 1) << 2);
        int g = h ^ ((n >> 1) & 1);
        int k0 = g * 16 + j * 2;
        __half2 h2 = __floats2half2_rn(s[k0][t], s[k0 + 1][t]);
        words[wo] = *(unsigned*)&h2;
    }
    uint4* dst = (uint4*)(wp + ((size_t)kt * Nd + n) * 32);
#pragma unroll
    for (int q = 0; q < 4; q++)
        dst[q] = make_uint4(words[q * 4], words[q * 4 + 1],
                            words[q * 4 + 2], words[q * 4 + 3]);
}

// ---------------- bulk-copy fp16 mma GEMM (4 warps of 64x64) ------------------
// C[128x128] = A_planes[rows base..][K] @ W_planes[n0..][K]
template <bool ROUTED, bool FFN2>
__global__ __launch_bounds__(128, 2)
void gemm_blk(const __half* __restrict__ Ap, int AR,
              const __half* __restrict__ Wpb,
              const float* __restrict__ biasbase,
              const float* __restrict__ xres,
              void* __restrict__ OutV, int OutR,
              int Kdim, int Ndim) {
    int e = ROUTED ? blockIdx.z : 0;
    int off0 = ROUTED ? g_off[e] : 0;
    int off1 = ROUTED ? g_end[e] : TT;
    int m0 = blockIdx.y * 128;
    int base = off0 + m0;                  // 128-aligned: hidx32 row-phase safe
    if (base >= off1) return;
    int n0 = blockIdx.x * 128;
    const __half* W = Wpb + (ROUTED ? (size_t)e * Kdim * Ndim : 0);
    const float* bias = biasbase + (ROUTED ? (size_t)e * Ndim : 0);

    extern __shared__ __align__(128) float sm[];
    uint32_t sb = smem_u32(sm);
    int* sorow = (int*)(sm + OFF_META / 4);
    float* swt = (float*)(sorow + 128);
    float* sbias = swt + 128;
    uint32_t mb = sb + OFF_META + 1536;

    int tid = threadIdx.x, wid = tid >> 5, lane = tid & 31;
    {   // all 128 threads stage metadata
        int row = base + tid;
        bool valid = row < off1;
        int orow; float wv = 1.0f;
        if (!ROUTED) orow = row;
        else if (!FFN2) orow = valid ? row : -1;
        else { orow = valid ? g_ptok[row] : -1; wv = valid ? g_pw[row] : 0.0f; }
        sorow[tid] = orow; swt[tid] = wv; sbias[tid] = bias[n0 + tid];
    }
    if (tid == 0)
        for (int s = 0; s < NSTAGE; s++) MBAR_INIT(mb + 8 * s, 1);
    __syncthreads();

    int NK = Kdim >> 6;                           // 64-K stages
    const __half* A0 = Ap + (size_t)base * 32;
    const __half* B0 = W + (size_t)n0 * 32;

    if (tid == 0) {
#pragma unroll
        for (int c = 0; c < NSTAGE - 1; c++) {
            uint32_t st = sb + c * STAGE_BYTES;
            EXPECT_TX(mb + 8 * c, 32768u);
            BULK8K(st,          A0 + (size_t)(2 * c) * AR * 32, mb + 8 * c);
            BULK8K(st + 8192,   A0 + (size_t)(2 * c + 1) * AR * 32, mb + 8 * c);
            BULK8K(st + 16384,  B0 + (size_t)(2 * c) * Ndim * 32, mb + 8 * c);
            BULK8K(st + 24576,  B0 + (size_t)(2 * c + 1) * Ndim * 32, mb + 8 * c);
        }
    }

    // 4 warps in 2x2: warp tile 64M x 64N
    int wm = wid & 1, wn = wid >> 1, lrow = lane >> 2, lcol = lane & 3;
    int rh = (lrow >> 1) & 1;
    float acc[4][8][4];
#pragma unroll
    for (int a = 0; a < 4; a++)
#pragma unroll
        for (int b = 0; b < 8; b++)
#pragma unroll
            for (int c = 0; c < 4; c++) acc[a][b][c] = 0.0f;

    uint32_t a_off = (uint32_t)((wm * 64 + lrow) * 64 + lcol * 8);
    uint32_t b_off = (uint32_t)(16384 + (wn * 64 + lrow) * 64 + lcol * 8);

    for (int kt = 0; kt < NK; kt++) {
        int slot = kt % NSTAGE;
        MBAR_WAIT(mb + 8 * slot, (kt / NSTAGE) & 1);
        uint32_t st = sb + slot * STAGE_BYTES;
#pragma unroll
        for (int pp = 0; pp < 2; pp++) {           // two 32-k planes
#pragma unroll
            for (int g = 0; g < 2; g++) {          // two k16 groups
                uint32_t ho = (uint32_t)(((g ^ rh) & 1) << 5);
                uint32_t ab = st + pp * 8192 + a_off + ho;
                uint32_t bb = st + pp * 8192 + b_off + ho;
                unsigned af[4][4];
#pragma unroll
                for (int tm = 0; tm < 4; tm++) {
                    uint32_t p = ab + tm * 1024;       // tm*16 rows * 64B
                    asm volatile("ld.shared.v2.b32 {%0,%1}, [%2];"
                                 : "=r"(af[tm][0]), "=r"(af[tm][2]) : "r"(p));
                    asm volatile("ld.shared.v2.b32 {%0,%1}, [%2];"
                                 : "=r"(af[tm][1]), "=r"(af[tm][3]) : "r"(p + 512));
                }
                unsigned bf[8][2];
#pragma unroll
                for (int tn = 0; tn < 8; tn++) {
                    asm volatile("ld.shared.v2.b32 {%0,%1}, [%2];"
                                 : "=r"(bf[tn][0]), "=r"(bf[tn][1])
                                 : "r"(bb + tn * 512));
                }
#pragma unroll
                for (int tm = 0; tm < 4; tm++)
#pragma unroll
                    for (int tn = 0; tn < 8; tn++)
                        mma_f16(acc[tm][tn], af[tm], bf[tn]);
            }
        }
        __syncthreads();
        int kl = kt + NSTAGE - 1;
        if (tid == 0 && kl < NK) {
            int sl = kl % NSTAGE;
            uint32_t st2 = sb + sl * STAGE_BYTES;
            EXPECT_TX(mb + 8 * sl, 32768u);
            BULK8K(st2,         A0 + (size_t)(2 * kl) * AR * 32, mb + 8 * sl);
            BULK8K(st2 + 8192,  A0 + (size_t)(2 * kl + 1) * AR * 32, mb + 8 * sl);
            BULK8K(st2 + 16384, B0 + (size_t)(2 * kl) * Ndim * 32, mb + 8 * sl);
            BULK8K(st2 + 24576, B0 + (size_t)(2 * kl + 1) * Ndim * 32, mb + 8 * sl);
        }
    }

    // epilogue
#pragma unroll
    for (int tm = 0; tm < 4; tm++) {
#pragma unroll
        for (int rr = 0; rr < 2; rr++) {
            int li = wm * 64 + tm * 16 + rr * 8 + lrow;
            int orow = sorow[li];
            if (orow < 0) continue;
            float wv = swt[li];
#pragma unroll
            for (int tn = 0; tn < 8; tn++) {
                int c0 = wn * 64 + tn * 8 + lcol * 2;
                float v0 = acc[tm][tn][rr * 2 + 0] + sbias[c0];
                float v1 = acc[tm][tn][rr * 2 + 1] + sbias[c0 + 1];
                if (!FFN2) {
                    // hidden: gelu -> fp16 pair packed into one 4B word
                    int gc = n0 + c0;
                    __half2 h2 = __floats2half2_rn(geluf(v0), geluf(v1));
                    int kl2 = gc & 31;
                    int g = (kl2 >> 4) & 1;
                    int j = (kl2 >> 1) & 7;
                    int slot2 = ((j & 3) << 1) | (j >> 2);
                    int h = g ^ ((orow >> 1) & 1);
                    unsigned* op = (unsigned*)OutV;
                    op[((size_t)(gc >> 5) * OutR + orow) * 16 + h * 8 + slot2] =
                        *(unsigned*)&h2;
                } else if (!ROUTED) {
                    float* Out = (float*)OutV;
                    size_t o = (size_t)orow * Ndim + n0 + c0;
                    Out[o]     = xres[o]     + v0;
                    Out[o + 1] = xres[o + 1] + v1;
                } else {
                    float* Out = (float*)OutV;
                    size_t o = (size_t)orow * Ndim + n0 + c0;
                    atomicAdd(&Out[o],     wv * v0);
                    atomicAdd(&Out[o + 1], wv * v1);
                }
            }
        }
    }
}

// ---------------- launch -----------------------------------------------------
extern "C" void kernel_launch(void* const* d_in, const int* in_sizes, int n_in,
                              void* d_out, int out_size) {
    const float* x      = (const float*)d_in[0];
    const float* time_c = (const float*)d_in[1];
    const float* ada_w  = (const float*)d_in[2];
    const float* ada_b  = (const float*)d_in[3];
    const float* gate_w = (const float*)d_in[4];
    const float* w1     = (const float*)d_in[5];
    const float* b1     = (const float*)d_in[6];
    const float* w2     = (const float*)d_in[7];
    const float* b2     = (const float*)d_in[8];
    const float* sw1    = (const float*)d_in[9];
    const float* sb1    = (const float*)d_in[10];
    const float* sw2    = (const float*)d_in[11];
    const float* sb2    = (const float*)d_in[12];
    float* out = (float*)d_out;

    __half *p_tph, *p_trh, *p_hsph, *p_hrph, *p_sw1P, *p_sw2P, *p_w1P, *p_w2P;
    cudaGetSymbolAddress((void**)&p_tph, g_tph);
    cudaGetSymbolAddress((void**)&p_trh, g_trh);
    cudaGetSymbolAddress((void**)&p_hsph, g_hsph);
    cudaGetSymbolAddress((void**)&p_hrph, g_hrph);
    cudaGetSymbolAddress((void**)&p_sw1P, g_sw1P);
    cudaGetSymbolAddress((void**)&p_sw2P, g_sw2P);
    cudaGetSymbolAddress((void**)&p_w1P, g_w1P);
    cudaGetSymbolAddress((void**)&p_w2P, g_w2P);

    cudaFuncSetAttribute(gemm_blk<false, false>,
                         cudaFuncAttributeMaxDynamicSharedMemorySize, SMEM_DYN);
    cudaFuncSetAttribute(gemm_blk<true, false>,
                         cudaFuncAttributeMaxDynamicSharedMemorySize, SMEM_DYN);
    cudaFuncSetAttribute(gemm_blk<false, true>,
                         cudaFuncAttributeMaxDynamicSharedMemorySize, SMEM_DYN);
    cudaFuncSetAttribute(gemm_blk<true, true>,
                         cudaFuncAttributeMaxDynamicSharedMemorySize, SMEM_DYN);

    init_kernel<<<1, 32>>>();
    cond_kernel<<<dim3(TWOD / 256, BB), 256>>>(time_c, ada_w, ada_b);
    ln_route_kernel<<<TT, 256>>>(x, gate_w);
    offsets_kernel<<<1, 32>>>();
    padinit_kernel<<<(RPAD + 255) / 256, 256>>>();
    fill_kernel<<<dim3(EE, TT / 256), 256>>>();
    gather_kernel<<<(RPAD * 32) / 256, 256>>>();

    prep_w<<<dim3(HH / 256, DD / 32, 1), 256>>>(sw1, p_sw1P, DD, HH);
    prep_w<<<dim3(DD / 256, HH / 32, 1), 256>>>(sw2, p_sw2P, HH, DD);
    prep_w<<<dim3(HH / 256, DD / 32, EE), 256>>>(w1, p_w1P, DD, HH);
    prep_w<<<dim3(DD / 256, HH / 32, EE), 256>>>(w2, p_w2P, HH, DD);

    // shared FFN1: hs_planes = fp16(gelu(t @ sw1 + sb1))
    gemm_blk<false, false><<<dim3(HH / 128, TT / 128, 1), 128, SMEM_DYN>>>(
        p_tph, TT, p_sw1P, sb1, nullptr, p_hsph, TT, DD, HH);
    // routed FFN1: hr_planes[p] = fp16(gelu(tr[p] @ w1[e] + b1[e]))
    gemm_blk<true, false><<<dim3(HH / 128, 64, EE), 128, SMEM_DYN>>>(
        p_trh, RPAD, p_w1P, b1, nullptr, p_hrph, RPAD, DD, HH);
    // shared FFN2 (+residual init): out = x + hs @ sw2 + sb2
    gemm_blk<false, true><<<dim3(DD / 128, TT / 128, 1), 128, SMEM_DYN>>>(
        p_hsph, TT, p_sw2P, sb2, x, out, 0, HH, DD);
    // routed FFN2: out[tok] += w * (hr[p] @ w2[e] + b2[e])
    gemm_blk<true, true><<<dim3(DD / 128, 64, EE), 128, SMEM_DYN>>>(
        p_hrph, RPAD, p_w2P, b2, nullptr, out, 0, HH, DD);
}

// round 16
// speedup vs baseline: 2.6061x; 1.0011x over previous
#include <cuda_runtime.h>
#include <cuda_fp16.h>
#include <math.h>
#include <stdint.h>

// Problem constants
#define BB 4
#define LL 2048
#define DD 1024
#define EE 8
#define HH 4096
#define TT 8192
#define TWOD 2048
#define EPSV 1e-6f
#define RPAD 17536              // padded routed rows (128-aligned expert segments)

// GEMM: CTA 128M x 128N, fp16 mma m16n8k16.
// stage = 64 K (two 32-k fp16 planes per operand), 32KB/stage, 3 stages.
// 4 warps of 64x64, 2 CTAs/SM.
#define STAGE_BYTES 32768
#define NSTAGE 3
#define OFF_META (NSTAGE * STAGE_BYTES)          // 98304
#define SMEM_DYN (OFF_META + 2048)               // 100352 bytes

// ---------------- device scratch ---------------------------------------------
__device__ float  g_cond[BB * TWOD];
__device__ __half g_tph[(size_t)32 * TT * 32];        // xn tokens, fp16 planes
__device__ __half g_trh[(size_t)32 * RPAD * 32];      // gathered tokens (p-order)
__device__ __half g_hsph[(size_t)128 * TT * 32];      // shared hidden planes
__device__ __half g_hrph[(size_t)128 * RPAD * 32];    // routed hidden planes
__device__ __half g_sw1P[(size_t)32 * HH * 32];
__device__ __half g_sw2P[(size_t)128 * DD * 32];
__device__ __half g_w1P[(size_t)EE * 32 * HH * 32];
__device__ __half g_w2P[(size_t)EE * 128 * DD * 32];
__device__ float  g_ypair[(size_t)RPAD * DD];         // routed FFN2 pair outputs
__device__ int    g_cnt[EE];
__device__ int    g_off[EE + 1];                      // 128-aligned starts
__device__ int    g_end[EE];                          // true ends
__device__ int    g_list[EE * TT];
__device__ float  g_pairw[2 * TT];
__device__ int    g_ptok[RPAD];
__device__ float  g_pw[RPAD];
__device__ int    g_ppos[2 * TT];                     // pair id -> p slot

// ---------------- helpers ----------------------------------------------------
__device__ __forceinline__ float geluf(float v) {
    float u = 0.7978845608028654f * (v + 0.044715f * v * v * v);
    return 0.5f * v * (1.0f + tanhf(u));
}

__device__ __forceinline__ uint32_t smem_u32(const void* p) {
    uint32_t a;
    asm("{ .reg .u64 t; cvta.to.shared.u64 t, %1; cvt.u32.u64 %0, t; }"
        : "=r"(a) : "l"(p));
    return a;
}

// fp16 plane row = 32 halves (64B) covering 32 k values = two k16 groups.
// Each 32B half-group holds 8 k-pairs at slot order [0,4,1,5,2,6,3,7];
// half-groups are swapped by bit1 of the row index (bank spread).
// NOTE: row-dependent — all tile bases must be 128-aligned.
__device__ __forceinline__ int hidx32(int r, int k) {
    int g = (k >> 4) & 1;
    int j = (k >> 1) & 7;
    int slot = ((j & 3) << 1) | (j >> 2);
    int h = g ^ ((r >> 1) & 1);
    return h * 16 + slot * 2 + (k & 1);
}

__device__ __forceinline__ void mma_f16(float* c, const unsigned* a, const unsigned* b) {
    asm volatile(
        "mma.sync.aligned.m16n8k16.row.col.f32.f16.f16.f32 "
        "{%0,%1,%2,%3}, {%4,%5,%6,%7}, {%8,%9}, {%0,%1,%2,%3};\n"
        : "+f"(c[0]), "+f"(c[1]), "+f"(c[2]), "+f"(c[3])
        : "r"(a[0]), "r"(a[1]), "r"(a[2]), "r"(a[3]), "r"(b[0]), "r"(b[1]));
}

#define MBAR_INIT(a, cnt) \
    asm volatile("mbarrier.init.shared.b64 [%0], %1;" :: "r"(a), "r"(cnt) : "memory")

#define EXPECT_TX(mbar, n) \
    asm volatile("mbarrier.arrive.expect_tx.shared.b64 _, [%0], %1;" \
                 :: "r"(mbar), "r"(n) : "memory")

#define BULK8K(dst, src, mbar) \
    asm volatile("cp.async.bulk.shared::cluster.global.mbarrier::complete_tx::bytes " \
                 "[%0], [%1], %2, [%3];" \
                 :: "r"(dst), "l"(src), "r"(8192u), "r"(mbar) : "memory")

#define MBAR_WAIT(mbar, par) do {                                              \
    uint32_t _m = (mbar); uint32_t _p = (par); uint32_t _d;                    \
    asm volatile("{\n\t.reg .pred p;\n\t"                                      \
        "mbarrier.try_wait.parity.acquire.cta.shared::cta.b64 p, [%1], %2;\n\t"\
        "selp.b32 %0, 1, 0, p;\n\t}" : "=r"(_d) : "r"(_m), "r"(_p) : "memory");\
    if (!_d) {                                                                 \
        asm volatile("{\n\t.reg .pred P1;\n\t"                                 \
            "W0_%=:\n\t"                                                       \
            "mbarrier.try_wait.parity.acquire.cta.shared::cta.b64 P1, [%0], %1, 0x989680;\n\t" \
            "@P1 bra.uni W1_%=;\n\t"                                           \
            "bra.uni W0_%=;\n\t"                                               \
            "W1_%=:\n\t}" :: "r"(_m), "r"(_p) : "memory");                     \
    }                                                                          \
} while (0)

// ---------------- small kernels ----------------------------------------------
__global__ void init_kernel() {
    if (threadIdx.x < EE) g_cnt[threadIdx.x] = 0;
}

__global__ void cond_kernel(const float* __restrict__ time_c,
                            const float* __restrict__ ada_w,
                            const float* __restrict__ ada_b) {
    __shared__ float s[DD];
    int b = blockIdx.y;
    for (int i = threadIdx.x; i < DD; i += blockDim.x) {
        float v = time_c[b * DD + i];
        s[i] = v / (1.0f + expf(-v));
    }
    __syncthreads();
    int col = blockIdx.x * 256 + threadIdx.x;
    float acc = 0.0f;
#pragma unroll 4
    for (int r = 0; r < DD; r++) acc += s[r] * ada_w[r * TWOD + col];
    g_cond[b * TWOD + col] = acc + ada_b[col];
}

__global__ void ln_route_kernel(const float* __restrict__ x,
                                const float* __restrict__ gate_w) {
    int tok = blockIdx.x;
    int b = tok / LL;
    const float* xr = x + (size_t)tok * DD;
    __shared__ float sx[DD];
    __shared__ float sred[16];
    __shared__ float smv[2];
    __shared__ float slog[EE];
    int tid = threadIdx.x, lane = tid & 31, w = tid >> 5;
    float lsum = 0.0f, lsq = 0.0f;
    for (int i = tid; i < DD; i += 256) {
        float v = xr[i];
        sx[i] = v; lsum += v; lsq += v * v;
    }
#pragma unroll
    for (int o = 16; o > 0; o >>= 1) {
        lsum += __shfl_down_sync(0xffffffffu, lsum, o);
        lsq  += __shfl_down_sync(0xffffffffu, lsq, o);
    }
    if (lane == 0) { sred[w] = lsum; sred[8 + w] = lsq; }
    __syncthreads();
    if (tid == 0) {
        float s = 0.0f, q = 0.0f;
        for (int i = 0; i < 8; i++) { s += sred[i]; q += sred[8 + i]; }
        float mean = s / (float)DD;
        float var = q / (float)DD - mean * mean;
        smv[0] = mean; smv[1] = rsqrtf(var + EPSV);
    }
    __syncthreads();
    float mean = smv[0], rstd = smv[1];
    const float* shiftp = g_cond + b * TWOD;
    const float* scalep = shiftp + DD;
    for (int i = tid; i < DD; i += 256) {
        float ln = (sx[i] - mean) * rstd;
        float xn = ln * (1.0f + scalep[i]) + shiftp[i];
        sx[i] = xn;
        g_tph[((size_t)(i >> 5) * TT + tok) * 32 + hidx32(tok, i & 31)] =
            __float2half_rn(xn);
    }
    __syncthreads();
    float acc = 0.0f;
    for (int r = lane; r < DD; r += 32) acc += sx[r] * gate_w[r * EE + w];
#pragma unroll
    for (int o = 16; o > 0; o >>= 1) acc += __shfl_down_sync(0xffffffffu, acc, o);
    if (lane == 0) slog[w] = acc;
    __syncthreads();
    if (tid == 0) {
        float m = slog[0];
        for (int e = 1; e < EE; e++) m = fmaxf(m, slog[e]);
        float p[EE];
        for (int e = 0; e < EE; e++) p[e] = expf(slog[e] - m);
        int i0 = 0; float v0 = p[0];
        for (int e = 1; e < EE; e++) if (p[e] > v0) { v0 = p[e]; i0 = e; }
        int i1 = -1; float v1 = -1.0f;
        for (int e = 0; e < EE; e++) if (e != i0 && p[e] > v1) { v1 = p[e]; i1 = e; }
        float inv = 1.0f / (v0 + v1);
        int pos0 = atomicAdd(&g_cnt[i0], 1);
        g_list[i0 * TT + pos0] = tok * 2;
        int pos1 = atomicAdd(&g_cnt[i1], 1);
        g_list[i1 * TT + pos1] = tok * 2 + 1;
        g_pairw[tok * 2] = v0 * inv;
        g_pairw[tok * 2 + 1] = v1 * inv;
    }
}

__global__ void offsets_kernel() {
    if (threadIdx.x == 0) {
        int s = 0;
        for (int e = 0; e < EE; e++) {
            g_off[e] = s;
            g_end[e] = s + g_cnt[e];
            s += (g_cnt[e] + 127) & ~127;      // 128-align each segment
        }
        g_off[EE] = s;
    }
}

__global__ void padinit_kernel() {
    int p = blockIdx.x * 256 + threadIdx.x;
    if (p < RPAD) { g_ptok[p] = 0; g_pw[p] = 0.0f; }
}

__global__ void fill_kernel() {
    int e = blockIdx.x;
    int pos = blockIdx.y * 256 + threadIdx.x;
    if (pos < g_cnt[e]) {
        int pair = g_list[e * TT + pos];
        int p = g_off[e] + pos;
        g_ptok[p] = pair >> 1;
        g_pw[p] = g_pairw[pair];
        g_ppos[pair] = p;
    }
}

// gather tokens into p-order planes; fix bit1 half-swap for new row index
__global__ void gather_kernel() {
    int id = blockIdx.x * 256 + threadIdx.x;      // RPAD*32 threads
    int p = id >> 5, kt = id & 31;
    int tok = g_ptok[p];
    int swap = ((tok ^ p) >> 1) & 1;
    const uint4* s = (const uint4*)(g_tph + ((size_t)kt * TT + tok) * 32);
    uint4 a = s[0], b = s[1], c = s[2], d = s[3];
    uint4* o = (uint4*)(g_trh + ((size_t)kt * RPAD + p) * 32);
    if (swap) { o[0] = c; o[1] = d; o[2] = a; o[3] = b; }
    else      { o[0] = a; o[1] = b; o[2] = c; o[3] = d; }
}

// weights [K][N] -> fp16 planes [kt32][n][32] with hidx32 layout
__global__ void prep_w(const float* __restrict__ W, __half* __restrict__ Wp,
                       int Kd, int Nd) {
    __shared__ float s[32][257];
    int e = blockIdx.z;
    const float* w = W + (size_t)e * Kd * Nd;
    __half* wp = Wp + (size_t)e * Kd * Nd;
    int kt = blockIdx.y, n0 = blockIdx.x * 256, t = threadIdx.x;
#pragma unroll
    for (int k = 0; k < 32; k++)
        s[k][t] = w[(size_t)(kt * 32 + k) * Nd + n0 + t];
    __syncthreads();
    int n = n0 + t;
    unsigned words[16];
#pragma unroll
    for (int wo = 0; wo < 16; wo++) {
        int h = wo >> 3;
        int slot = wo & 7;
        int j = ((slot >> 1) & 3) | ((slot & 1) << 2);
        int g = h ^ ((n >> 1) & 1);
        int k0 = g * 16 + j * 2;
        __half2 h2 = __floats2half2_rn(s[k0][t], s[k0 + 1][t]);
        words[wo] = *(unsigned*)&h2;
    }
    uint4* dst = (uint4*)(wp + ((size_t)kt * Nd + n) * 32);
#pragma unroll
    for (int q = 0; q < 4; q++)
        dst[q] = make_uint4(words[q * 4], words[q * 4 + 1],
                            words[q * 4 + 2], words[q * 4 + 3]);
}

// final combine: out[tok] += w0 * y[p0] + w1 * y[p1]
__global__ void combine_kernel(float* __restrict__ out) {
    int tok = blockIdx.x;
    int c = threadIdx.x * 4;
    int p0 = g_ppos[tok * 2], p1 = g_ppos[tok * 2 + 1];
    float w0 = g_pw[p0], w1 = g_pw[p1];
    float4 o = *(float4*)(out + (size_t)tok * DD + c);
    float4 a = *(const float4*)(g_ypair + (size_t)p0 * DD + c);
    float4 b = *(const float4*)(g_ypair + (size_t)p1 * DD + c);
    o.x += w0 * a.x + w1 * b.x;
    o.y += w0 * a.y + w1 * b.y;
    o.z += w0 * a.z + w1 * b.z;
    o.w += w0 * a.w + w1 * b.w;
    *(float4*)(out + (size_t)tok * DD + c) = o;
}

// ---------------- merged bulk-copy fp16 mma GEMM ------------------------------
// z=0: shared expert; z=1..8: routed expert z-1.
// FFN1: hidden = fp16(gelu(A @ W + b)) into fp16 planes.
// FFN2 shared: out = x + A @ W + b.   FFN2 routed: ypair[row] = A @ W + b.
template <bool FFN2K>
__global__ __launch_bounds__(128, 2)
void gemm_u(const __half* __restrict__ Ash, const __half* __restrict__ Art,
            const __half* __restrict__ Wsh, const __half* __restrict__ Wrt,
            const float* __restrict__ bsh, const float* __restrict__ brt,
            const float* __restrict__ xres,
            void* __restrict__ OutSh, void* __restrict__ OutRt,
            int Kdim, int Ndim) {
    int z = blockIdx.z;
    bool shex = (z == 0);
    int e = z - 1;
    int off1 = shex ? TT : g_end[e];
    int base = (shex ? 0 : g_off[e]) + blockIdx.y * 128;   // 128-aligned
    if (base >= off1) return;
    int AR = shex ? TT : RPAD;
    const __half* Ap = shex ? Ash : Art;
    const __half* W = shex ? Wsh : Wrt + (size_t)e * Kdim * Ndim;
    const float* bias = shex ? bsh : brt + e * Ndim;
    int n0 = blockIdx.x * 128;

    extern __shared__ __align__(128) float sm[];
    uint32_t sb = smem_u32(sm);
    int* sorow = (int*)(sm + OFF_META / 4);
    float* sbias = (float*)(sorow + 128);
    uint32_t mb = sb + OFF_META + 1536;

    int tid = threadIdx.x, wid = tid >> 5, lane = tid & 31;
    {
        int row = base + tid;
        sorow[tid] = (row < off1) ? row : -1;
        sbias[tid] = bias[n0 + tid];
    }
    if (tid == 0)
        for (int s = 0; s < NSTAGE; s++) MBAR_INIT(mb + 8 * s, 1);
    __syncthreads();

    int NK = Kdim >> 6;
    const __half* A0 = Ap + (size_t)base * 32;
    const __half* B0 = W + (size_t)n0 * 32;

    if (tid == 0) {
#pragma unroll
        for (int c = 0; c < NSTAGE - 1; c++) {
            uint32_t st = sb + c * STAGE_BYTES;
            EXPECT_TX(mb + 8 * c, 32768u);
            BULK8K(st,          A0 + (size_t)(2 * c) * AR * 32, mb + 8 * c);
            BULK8K(st + 8192,   A0 + (size_t)(2 * c + 1) * AR * 32, mb + 8 * c);
            BULK8K(st + 16384,  B0 + (size_t)(2 * c) * Ndim * 32, mb + 8 * c);
            BULK8K(st + 24576,  B0 + (size_t)(2 * c + 1) * Ndim * 32, mb + 8 * c);
        }
    }

    int wm = wid & 1, wn = wid >> 1, lrow = lane >> 2, lcol = lane & 3;
    int rh = (lrow >> 1) & 1;
    float acc[4][8][4];
#pragma unroll
    for (int a = 0; a < 4; a++)
#pragma unroll
        for (int b = 0; b < 8; b++)
#pragma unroll
            for (int c = 0; c < 4; c++) acc[a][b][c] = 0.0f;

    uint32_t a_off = (uint32_t)((wm * 64 + lrow) * 64 + lcol * 8);
    uint32_t b_off = (uint32_t)(16384 + (wn * 64 + lrow) * 64 + lcol * 8);

    for (int kt = 0; kt < NK; kt++) {
        // refill ahead (slot's consumers synced at end of iteration kt-1)
        int kl = kt + NSTAGE - 1;
        if (tid == 0 && kl < NK) {
            int sl = kl % NSTAGE;
            uint32_t st2 = sb + sl * STAGE_BYTES;
            EXPECT_TX(mb + 8 * sl, 32768u);
            BULK8K(st2,         A0 + (size_t)(2 * kl) * AR * 32, mb + 8 * sl);
            BULK8K(st2 + 8192,  A0 + (size_t)(2 * kl + 1) * AR * 32, mb + 8 * sl);
            BULK8K(st2 + 16384, B0 + (size_t)(2 * kl) * Ndim * 32, mb + 8 * sl);
            BULK8K(st2 + 24576, B0 + (size_t)(2 * kl + 1) * Ndim * 32, mb + 8 * sl);
        }
        int slot = kt % NSTAGE;
        MBAR_WAIT(mb + 8 * slot, (kt / NSTAGE) & 1);
        uint32_t st = sb + slot * STAGE_BYTES;
#pragma unroll
        for (int pp = 0; pp < 2; pp++) {
#pragma unroll
            for (int g = 0; g < 2; g++) {
                uint32_t ho = (uint32_t)(((g ^ rh) & 1) << 5);
                uint32_t ab = st + pp * 8192 + a_off + ho;
                uint32_t bb = st + pp * 8192 + b_off + ho;
                unsigned af[4][4];
#pragma unroll
                for (int tm = 0; tm < 4; tm++) {
                    uint32_t p = ab + tm * 1024;
                    asm volatile("ld.shared.v2.b32 {%0,%1}, [%2];"
                                 : "=r"(af[tm][0]), "=r"(af[tm][2]) : "r"(p));
                    asm volatile("ld.shared.v2.b32 {%0,%1}, [%2];"
                                 : "=r"(af[tm][1]), "=r"(af[tm][3]) : "r"(p + 512));
                }
                unsigned bf[8][2];
#pragma unroll
                for (int tn = 0; tn < 8; tn++) {
                    asm volatile("ld.shared.v2.b32 {%0,%1}, [%2];"
                                 : "=r"(bf[tn][0]), "=r"(bf[tn][1])
                                 : "r"(bb + tn * 512));
                }
#pragma unroll
                for (int tm = 0; tm < 4; tm++)
#pragma unroll
                    for (int tn = 0; tn < 8; tn++)
                        mma_f16(acc[tm][tn], af[tm], bf[tn]);
            }
        }
        __syncthreads();
    }

    // epilogue
    int OutR = shex ? TT : RPAD;
    unsigned* oph = (unsigned*)(shex ? OutSh : OutRt);
#pragma unroll
    for (int tm = 0; tm < 4; tm++) {
#pragma unroll
        for (int rr = 0; rr < 2; rr++) {
            int li = wm * 64 + tm * 16 + rr * 8 + lrow;
            int orow = sorow[li];
            if (orow < 0) continue;
#pragma unroll
            for (int tn = 0; tn < 8; tn++) {
                int c0 = wn * 64 + tn * 8 + lcol * 2;
                float v0 = acc[tm][tn][rr * 2 + 0] + sbias[c0];
                float v1 = acc[tm][tn][rr * 2 + 1] + sbias[c0 + 1];
                if (!FFN2K) {
                    int gc = n0 + c0;
                    __half2 h2 = __floats2half2_rn(geluf(v0), geluf(v1));
                    int kl2 = gc & 31;
                    int g = (kl2 >> 4) & 1;
                    int j = (kl2 >> 1) & 7;
                    int slot2 = ((j & 3) << 1) | (j >> 2);
                    int h = g ^ ((orow >> 1) & 1);
                    oph[((size_t)(gc >> 5) * OutR + orow) * 16 + h * 8 + slot2] =
                        *(unsigned*)&h2;
                } else if (shex) {
                    float* Out = (float*)OutSh;
                    size_t o = (size_t)orow * Ndim + n0 + c0;
                    Out[o]     = xres[o]     + v0;
                    Out[o + 1] = xres[o + 1] + v1;
                } else {
                    float* Out = (float*)OutRt;
                    size_t o = (size_t)orow * Ndim + n0 + c0;
                    Out[o]     = v0;
                    Out[o + 1] = v1;
                }
            }
        }
    }
}

// ---------------- launch -----------------------------------------------------
extern "C" void kernel_launch(void* const* d_in, const int* in_sizes, int n_in,
                              void* d_out, int out_size) {
    const float* x      = (const float*)d_in[0];
    const float* time_c = (const float*)d_in[1];
    const float* ada_w  = (const float*)d_in[2];
    const float* ada_b  = (const float*)d_in[3];
    const float* gate_w = (const float*)d_in[4];
    const float* w1     = (const float*)d_in[5];
    const float* b1     = (const float*)d_in[6];
    const float* w2     = (const float*)d_in[7];
    const float* b2     = (const float*)d_in[8];
    const float* sw1    = (const float*)d_in[9];
    const float* sb1    = (const float*)d_in[10];
    const float* sw2    = (const float*)d_in[11];
    const float* sb2    = (const float*)d_in[12];
    float* out = (float*)d_out;

    __half *p_tph, *p_trh, *p_hsph, *p_hrph, *p_sw1P, *p_sw2P, *p_w1P, *p_w2P;
    float* p_ypair;
    cudaGetSymbolAddress((void**)&p_tph, g_tph);
    cudaGetSymbolAddress((void**)&p_trh, g_trh);
    cudaGetSymbolAddress((void**)&p_hsph, g_hsph);
    cudaGetSymbolAddress((void**)&p_hrph, g_hrph);
    cudaGetSymbolAddress((void**)&p_sw1P, g_sw1P);
    cudaGetSymbolAddress((void**)&p_sw2P, g_sw2P);
    cudaGetSymbolAddress((void**)&p_w1P, g_w1P);
    cudaGetSymbolAddress((void**)&p_w2P, g_w2P);
    cudaGetSymbolAddress((void**)&p_ypair, g_ypair);

    cudaFuncSetAttribute(gemm_u<false>,
                         cudaFuncAttributeMaxDynamicSharedMemorySize, SMEM_DYN);
    cudaFuncSetAttribute(gemm_u<true>,
                         cudaFuncAttributeMaxDynamicSharedMemorySize, SMEM_DYN);

    init_kernel<<<1, 32>>>();
    cond_kernel<<<dim3(TWOD / 256, BB), 256>>>(time_c, ada_w, ada_b);
    ln_route_kernel<<<TT, 256>>>(x, gate_w);
    offsets_kernel<<<1, 32>>>();
    padinit_kernel<<<(RPAD + 255) / 256, 256>>>();
    fill_kernel<<<dim3(EE, TT / 256), 256>>>();
    gather_kernel<<<(RPAD * 32) / 256, 256>>>();

    prep_w<<<dim3(HH / 256, DD / 32, 1), 256>>>(sw1, p_sw1P, DD, HH);
    prep_w<<<dim3(DD / 256, HH / 32, 1), 256>>>(sw2, p_sw2P, HH, DD);
    prep_w<<<dim3(HH / 256, DD / 32, EE), 256>>>(w1, p_w1P, DD, HH);
    prep_w<<<dim3(DD / 256, HH / 32, EE), 256>>>(w2, p_w2P, HH, DD);

    // FFN1 (shared z=0 + routed z=1..8): hidden planes
    gemm_u<false><<<dim3(HH / 128, TT / 128, EE + 1), 128, SMEM_DYN>>>(
        p_tph, p_trh, p_sw1P, p_w1P, sb1, b1, nullptr,
        p_hsph, p_hrph, DD, HH);
    // FFN2 (shared z=0 writes out with residual; routed writes ypair)
    gemm_u<true><<<dim3(DD / 128, TT / 128, EE + 1), 128, SMEM_DYN>>>(
        p_hsph, p_hrph, p_sw2P, p_w2P, sb2, b2, x,
        out, p_ypair, HH, DD);
    // out[tok] += w0*ypair[p0] + w1*ypair[p1]
    combine_kernel<<<TT, 256>>>(out);
}